// round 7
// baseline (speedup 1.0000x reference)
#include <cuda_runtime.h>

static constexpr long kQSize = 256L * 128 * 512;        // 16,777,216
static constexpr long kAttn  = 8L * 256 * 128 * 256;    // 67,108,864

__device__ float g_lnL[kQSize];
__device__ float g_lnR[kQSize];
__device__ float g_q[kQSize];          // [w][n][c], pre-scaled by 0.125
__device__ float g_kv[2 * kQSize];     // [w][n][k(0:512)|v(512:1024)]
__device__ float g_posp[511 * 1024];   // [p][q_r*0.125 (0:512) | k_r (512:1024)]
__device__ float g_vo[kQSize];         // [w][n][c]
__device__ float g_A12[kAttn];         // [e][w][n][v]  scores -> probs
__device__ float g_T3[kAttn];          // [e][v][w][n]

__device__ __forceinline__ float4 ld4(const float* p) {
  return *reinterpret_cast<const float4*>(p);
}
__device__ __forceinline__ unsigned f2tf(float x) {
  unsigned r;
  asm("cvt.rna.tf32.f32 %0, %1;" : "=r"(r) : "f"(x));
  return r;
}
__device__ __forceinline__ void mma8(float (&d)[4], const unsigned (&a)[4],
                                     const unsigned (&b)[2]) {
  asm("mma.sync.aligned.m16n8k8.row.col.f32.tf32.tf32.f32 "
      "{%0,%1,%2,%3}, {%4,%5,%6,%7}, {%8,%9}, {%0,%1,%2,%3};"
      : "+f"(d[0]), "+f"(d[1]), "+f"(d[2]), "+f"(d[3])
      : "r"(a[0]), "r"(a[1]), "r"(a[2]), "r"(a[3]), "r"(b[0]), "r"(b[1]));
}
__device__ __forceinline__ void cpa16(float* smem_dst, const float* g, bool pred) {
  unsigned d = (unsigned)__cvta_generic_to_shared(smem_dst);
  int sz = pred ? 16 : 0;
  asm volatile("cp.async.cg.shared.global [%0], [%1], 16, %2;"
               :: "r"(d), "l"(g), "r"(sz));
}
__device__ __forceinline__ void cpa_commit() {
  asm volatile("cp.async.commit_group;" ::: "memory");
}
__device__ __forceinline__ void cpa_wait1() {
  asm volatile("cp.async.wait_group 1;" ::: "memory");
}

// ---------------- LayerNorm: one block per 512-float row ----------------
__global__ void __launch_bounds__(128) ln_kernel(const float* __restrict__ fl,
                                                 const float* __restrict__ fr,
                                                 const float* __restrict__ lw,
                                                 const float* __restrict__ lb) {
  long row = blockIdx.x;
  const float* src;
  float* dst;
  if (row < 32768) { src = fl + row * 512;           dst = g_lnL + row * 512; }
  else             { src = fr + (row - 32768) * 512; dst = g_lnR + (row - 32768) * 512; }
  int t = threadIdx.x;
  float4 x = ld4(src + t * 4);
  float s  = x.x + x.y + x.z + x.w;
  float q2 = x.x * x.x + x.y * x.y + x.z * x.z + x.w * x.w;
#pragma unroll
  for (int o = 16; o > 0; o >>= 1) {
    s  += __shfl_xor_sync(0xffffffffu, s, o);
    q2 += __shfl_xor_sync(0xffffffffu, q2, o);
  }
  __shared__ float ss[4], sq[4];
  if ((t & 31) == 0) { ss[t >> 5] = s; sq[t >> 5] = q2; }
  __syncthreads();
  s  = ss[0] + ss[1] + ss[2] + ss[3];
  q2 = sq[0] + sq[1] + sq[2] + sq[3];
  float mean = s * (1.f / 512.f);
  float var  = q2 * (1.f / 512.f) - mean * mean;
  float rstd = rsqrtf(var + 1e-5f);
  float4 wv = ld4(lw + t * 4), bv = ld4(lb + t * 4);
  float4 o;
  o.x = (x.x - mean) * rstd * wv.x + bv.x;
  o.y = (x.y - mean) * rstd * wv.y + bv.y;
  o.z = (x.z - mean) * rstd * wv.z + bv.z;
  o.w = (x.w - mean) * rstd * wv.w + bv.w;
  *reinterpret_cast<float4*>(dst + t * 4) = o;
}

// ------------- Tensor-core tf32 GEMM, 3-stage cp.async pipeline -------------
// 0: q = lnL@Wq^T (+b)*0.125 -> g_q         1: kv = lnR@Wkv^T + b -> g_kv
// 2: posp = pos@W[:1024]^T + b (cols<512 *0.125), M=511 guarded -> g_posp
// 3: T1 per (n,e): q.k^T -> A12             4: T2 per (e,w): q.kr^T += A12 (gather B)
// 5: T3 per (e,v): qr.k^T -> T3 (gather A)  6: AV per (n,e): P@V (NN) -> g_vo
// 7: out = vo@Wo^T + b + resid -> d_out
template <int MODE, int BM, int BN>
__global__ void __launch_bounds__(256)
gemm_k(const float* __restrict__ pA, const float* __restrict__ pB,
       const float* __restrict__ pbias, const float* __restrict__ presid,
       const int* __restrict__ pidx, float* __restrict__ pC) {
  constexpr int WGN = BN / 32;       // warps along n
  constexpr int WGM = 8 / WGN;       // warps along m
  constexpr int WM  = BM / WGM;      // rows per warp
  constexpr int MT  = WM / 16;       // 16-row mma tiles per warp
  constexpr int ASZ = BM * 20;       // floats per A stage
  constexpr int BSZ = (MODE == 6) ? 16 * 136 : BN * 20;
  constexpr int NA  = (BM * 16) / 1024;   // cp.async per thread (A)
  constexpr int NB  = (BN * 16) / 1024;   // cp.async per thread (B)
  extern __shared__ float dsm[];
  float* Asm = dsm;                  // [3][ASZ]
  float* Bsm = dsm + 3 * ASZ;        // [3][BSZ]

  const int tid   = threadIdx.x;
  const int warp  = tid >> 5;
  const int lane  = tid & 31;
  const int gid   = lane >> 2;
  const int tg    = lane & 3;
  const int wm0   = (warp / WGN) * WM;
  const int wn0   = (warp % WGN) * 32;
  const int i0 = blockIdx.y * BM;
  const int j0 = blockIdx.x * BN;
  const int z  = blockIdx.z;

  const float* A = nullptr;
  const float* B = nullptr;
  float* C = nullptr;
  long lda = 0, ldb = 0, ldc = 0;
  int K = 0, e = 0, bb = 0;

  if constexpr (MODE == 0) { A = g_lnL; lda = 512; K = 512; B = pB; ldb = 512; C = g_q; ldc = 512; }
  else if constexpr (MODE == 1) { A = g_lnR; lda = 512; K = 512; B = pB; ldb = 512; C = g_kv; ldc = 1024; }
  else if constexpr (MODE == 2) { A = pA; lda = 512; K = 512; B = pB; ldb = 512; C = g_posp; ldc = 1024; }
  else if constexpr (MODE == 3) { bb = z >> 3; e = z & 7;
    A = g_q + (long)bb * 512 + e * 64; lda = 65536; K = 64;
    B = g_kv + (long)bb * 1024 + e * 64; ldb = 131072;
    C = g_A12 + (long)e * 8388608 + (long)bb * 256; ldc = 32768; }
  else if constexpr (MODE == 4) { e = z >> 8; bb = z & 255;
    A = g_q + (long)bb * 65536 + e * 64; lda = 512; K = 64;
    C = g_A12 + (long)e * 8388608 + (long)bb * 32768; ldc = 256; }
  else if constexpr (MODE == 5) { e = z >> 8; bb = z & 255;
    B = g_kv + (long)bb * 131072 + e * 64; ldb = 1024; K = 64;
    C = g_T3 + ((long)e * 256 + bb) * 32768; ldc = 128; }
  else if constexpr (MODE == 6) { bb = z >> 3; e = z & 7;
    A = g_A12 + (long)e * 8388608 + (long)bb * 256; lda = 32768; K = 256;
    B = g_kv + (long)bb * 1024 + 512 + e * 64; ldb = 131072;
    C = g_vo + (long)bb * 512 + e * 64; ldc = 65536; }
  else { A = g_vo; lda = 512; K = 512; B = pB; ldb = 512; C = pC; ldc = 512; }

  auto issue_tiles = [&](int k0, int stage) {
    float* dstA = Asm + stage * ASZ;
    float* dstB = Bsm + stage * BSZ;
#pragma unroll
    for (int it = 0; it < NA; ++it) {
      int t = (tid + it * 256) * 4;
      int i = t >> 4, kk = t & 15;
      float* d = &dstA[i * 20 + kk];
      if constexpr (MODE == 5) {
        int gi = pidx[(i0 + i) * 256 + bb];
        cpa16(d, g_posp + (long)gi * 1024 + e * 64 + k0 + kk, true);
      } else if constexpr (MODE == 2) {
        cpa16(d, A + (long)(i0 + i) * lda + k0 + kk, i0 + i < 511);
      } else {
        cpa16(d, A + (long)(i0 + i) * lda + k0 + kk, true);
      }
    }
#pragma unroll
    for (int it = 0; it < NB; ++it) {
      int t = (tid + it * 256) * 4;
      if constexpr (MODE == 6) {
        int kk = t / BN, j = t % BN;
        cpa16(&dstB[kk * 136 + j], B + (long)(k0 + kk) * ldb + j0 + j, true);
      } else if constexpr (MODE == 4) {
        int j = t >> 4, kk = t & 15;
        int gi = pidx[bb * 256 + j0 + j];
        cpa16(&dstB[j * 20 + kk], g_posp + (long)gi * 1024 + 512 + e * 64 + k0 + kk, true);
      } else {
        int j = t >> 4, kk = t & 15;
        cpa16(&dstB[j * 20 + kk], B + (long)(j0 + j) * ldb + k0 + kk, true);
      }
    }
  };

  float acc[MT][4][4];
#pragma unroll
  for (int m = 0; m < MT; ++m)
#pragma unroll
    for (int n = 0; n < 4; ++n)
#pragma unroll
      for (int r = 0; r < 4; ++r) acc[m][n][r] = 0.f;

  const int NIT = K / 16;
  issue_tiles(0, 0);  cpa_commit();
  issue_tiles(16, 1); cpa_commit();

  for (int itn = 0; itn < NIT; ++itn) {
    cpa_wait1();
    __syncthreads();
    int nxt = itn + 2;
    if (nxt < NIT) issue_tiles(nxt * 16, nxt % 3);
    cpa_commit();

    const int cur = itn % 3;
    const float* ap = Asm + cur * ASZ;
    const float* bp = Bsm + cur * BSZ;
#pragma unroll
    for (int ks = 0; ks < 2; ++ks) {
      const int kb = ks * 8;
      unsigned a[MT][4], b[4][2];
#pragma unroll
      for (int mt = 0; mt < MT; ++mt) {
        int r = wm0 + mt * 16 + gid;
        a[mt][0] = f2tf(ap[r * 20 + kb + tg]);
        a[mt][1] = f2tf(ap[(r + 8) * 20 + kb + tg]);
        a[mt][2] = f2tf(ap[r * 20 + kb + tg + 4]);
        a[mt][3] = f2tf(ap[(r + 8) * 20 + kb + tg + 4]);
      }
#pragma unroll
      for (int nt = 0; nt < 4; ++nt) {
        int cn = wn0 + nt * 8 + gid;
        if constexpr (MODE == 6) {
          b[nt][0] = f2tf(bp[(kb + tg) * 136 + cn]);
          b[nt][1] = f2tf(bp[(kb + tg + 4) * 136 + cn]);
        } else {
          b[nt][0] = f2tf(bp[cn * 20 + kb + tg]);
          b[nt][1] = f2tf(bp[cn * 20 + kb + tg + 4]);
        }
      }
#pragma unroll
      for (int mt = 0; mt < MT; ++mt)
#pragma unroll
        for (int nt = 0; nt < 4; ++nt) mma8(acc[mt][nt], a[mt], b[nt]);
    }
  }

  // ---- epilogue: each thread owns pairs (i, j), (i, j+1) and (i+8, ...) ----
#pragma unroll
  for (int mt = 0; mt < MT; ++mt) {
#pragma unroll
    for (int nt = 0; nt < 4; ++nt) {
      int j = j0 + wn0 + nt * 8 + 2 * tg;
#pragma unroll
      for (int h = 0; h < 2; ++h) {
        int i = i0 + wm0 + mt * 16 + gid + h * 8;
        if constexpr (MODE == 2) { if (i >= 511) continue; }
        float v0 = acc[mt][nt][h * 2 + 0];
        float v1 = acc[mt][nt][h * 2 + 1];
        float* cp = C + (long)i * ldc + j;
        if constexpr (MODE == 0) {
          float2 bv = *reinterpret_cast<const float2*>(pbias + j);
          v0 = (v0 + bv.x) * 0.125f; v1 = (v1 + bv.y) * 0.125f;
        } else if constexpr (MODE == 1) {
          float2 bv = *reinterpret_cast<const float2*>(pbias + j);
          v0 += bv.x; v1 += bv.y;
        } else if constexpr (MODE == 2) {
          float2 bv = *reinterpret_cast<const float2*>(pbias + j);
          float sc = (j < 512) ? 0.125f : 1.0f;
          v0 = (v0 + bv.x) * sc; v1 = (v1 + bv.y) * sc;
        } else if constexpr (MODE == 4) {
          float2 o = *reinterpret_cast<const float2*>(cp);
          v0 += o.x; v1 += o.y;
        } else if constexpr (MODE == 7) {
          float2 bv = *reinterpret_cast<const float2*>(pbias + j);
          float2 rv = *reinterpret_cast<const float2*>(presid + (long)i * 512 + j);
          v0 += bv.x + rv.x; v1 += bv.y + rv.y;
        }
        *reinterpret_cast<float2*>(cp) = make_float2(v0, v1);
      }
    }
  }
}

// ------- Fused T3-transpose + raw_attn + softmax -------
// grid (256 w, 16), block 256 = 8 warps. Each block handles (w, n0=8 rows).
// Phase 1: stage T3[e][v][w][n0:n0+8] into smem ts[e][nj][264] — each (e,v)
//   read is 8 contiguous floats = one 32B sector (100% sector efficiency).
// Phase 2: warp nj handles row n=n0+nj: for each e, read A12 row coalesced,
//   add T3 row from smem (float4, conflict-free), accumulate raw, softmax,
//   write probs back to A12.
__global__ void __launch_bounds__(256) t3_raw_sm_kernel(float* __restrict__ out2) {
  extern __shared__ float ts[];   // [8 e][8 nj][264]
  const int w   = blockIdx.x;
  const int n0  = blockIdx.y * 8;
  const int tid = threadIdx.x;

#pragma unroll
  for (int it = 0; it < 8; ++it) {
    int p = tid + it * 256;              // (e,v) pair id
    int e = p >> 8, v = p & 255;
    const float* src = g_T3 + ((long)e * 256 + v) * 32768 + (long)w * 128 + n0;
    float4 x0 = ld4(src);
    float4 x1 = ld4(src + 4);
    float* d = ts + (e * 8) * 264 + v;   // + nj*264 per element
    d[0 * 264] = x0.x; d[1 * 264] = x0.y; d[2 * 264] = x0.z; d[3 * 264] = x0.w;
    d[4 * 264] = x1.x; d[5 * 264] = x1.y; d[6 * 264] = x1.z; d[7 * 264] = x1.w;
  }
  __syncthreads();

  const int nj   = tid >> 5;
  const int lane = tid & 31;
  const int n    = n0 + nj;

  float raw0 = 0.f, raw1 = 0.f, raw2 = 0.f, raw3 = 0.f;
  float raw4 = 0.f, raw5 = 0.f, raw6 = 0.f, raw7 = 0.f;

#pragma unroll
  for (int e = 0; e < 8; ++e) {
    float* p = g_A12 + (long)e * 8388608 + (long)w * 32768 + n * 256;
    const float* tr = ts + (e * 8 + nj) * 264;
    float4 a = ld4(p + lane * 4);
    float4 b = ld4(p + 128 + lane * 4);
    float4 ta = ld4(tr + lane * 4);
    float4 tb = ld4(tr + 128 + lane * 4);
    a.x += ta.x; a.y += ta.y; a.z += ta.z; a.w += ta.w;
    b.x += tb.x; b.y += tb.y; b.z += tb.z; b.w += tb.w;
    raw0 += a.x; raw1 += a.y; raw2 += a.z; raw3 += a.w;
    raw4 += b.x; raw5 += b.y; raw6 += b.z; raw7 += b.w;
    float mx = fmaxf(fmaxf(fmaxf(a.x, a.y), fmaxf(a.z, a.w)),
                     fmaxf(fmaxf(b.x, b.y), fmaxf(b.z, b.w)));
#pragma unroll
    for (int o = 16; o > 0; o >>= 1) mx = fmaxf(mx, __shfl_xor_sync(0xffffffffu, mx, o));
    a.x = __expf(a.x - mx); a.y = __expf(a.y - mx);
    a.z = __expf(a.z - mx); a.w = __expf(a.w - mx);
    b.x = __expf(b.x - mx); b.y = __expf(b.y - mx);
    b.z = __expf(b.z - mx); b.w = __expf(b.w - mx);
    float s = a.x + a.y + a.z + a.w + b.x + b.y + b.z + b.w;
#pragma unroll
    for (int o = 16; o > 0; o >>= 1) s += __shfl_xor_sync(0xffffffffu, s, o);
    float inv = 1.0f / s;
    a.x *= inv; a.y *= inv; a.z *= inv; a.w *= inv;
    b.x *= inv; b.y *= inv; b.z *= inv; b.w *= inv;
    *reinterpret_cast<float4*>(p + lane * 4) = a;
    *reinterpret_cast<float4*>(p + 128 + lane * 4) = b;
  }

  float* rp = out2 + ((long)n * 256 + w) * 256;
  *reinterpret_cast<float4*>(rp + lane * 4) = make_float4(raw0, raw1, raw2, raw3);
  *reinterpret_cast<float4*>(rp + 128 + lane * 4) = make_float4(raw4, raw5, raw6, raw7);
}

extern "C" void kernel_launch(void* const* d_in, const int* in_sizes, int n_in,
                              void* d_out, int out_size) {
  const float* feat_left   = (const float*)d_in[0];
  const float* feat_right  = (const float*)d_in[1];
  const float* pos         = (const float*)d_in[2];
  const int*   pos_indexes = (const int*)d_in[3];
  const float* ln_w        = (const float*)d_in[4];
  const float* ln_b        = (const float*)d_in[5];
  const float* in_proj_w   = (const float*)d_in[6];
  const float* in_proj_b   = (const float*)d_in[7];
  const float* out_w       = (const float*)d_in[8];
  const float* out_b       = (const float*)d_in[9];
  float* out = (float*)d_out;

  constexpr int S128 = 3 * (128 * 20 + 128 * 20) * 4;   // 61440
  constexpr int S64  = 3 * (64 * 20 + 64 * 20) * 4;     // 30720
  constexpr int S6   = 3 * (128 * 20 + 16 * 136) * 4;   // 56832
  constexpr int ST3  = 8 * 8 * 264 * 4;                 // 67584
  cudaFuncSetAttribute(gemm_k<0, 128, 128>, cudaFuncAttributeMaxDynamicSharedMemorySize, S128);
  cudaFuncSetAttribute(gemm_k<1, 128, 128>, cudaFuncAttributeMaxDynamicSharedMemorySize, S128);
  cudaFuncSetAttribute(gemm_k<3, 128, 128>, cudaFuncAttributeMaxDynamicSharedMemorySize, S128);
  cudaFuncSetAttribute(gemm_k<4, 128, 128>, cudaFuncAttributeMaxDynamicSharedMemorySize, S128);
  cudaFuncSetAttribute(gemm_k<5, 128, 128>, cudaFuncAttributeMaxDynamicSharedMemorySize, S128);
  cudaFuncSetAttribute(gemm_k<7, 128, 128>, cudaFuncAttributeMaxDynamicSharedMemorySize, S128);
  cudaFuncSetAttribute(gemm_k<6, 128, 64>,  cudaFuncAttributeMaxDynamicSharedMemorySize, S6);
  cudaFuncSetAttribute(t3_raw_sm_kernel,    cudaFuncAttributeMaxDynamicSharedMemorySize, ST3);

  ln_kernel<<<65536, 128>>>(feat_left, feat_right, ln_w, ln_b);

  gemm_k<0, 128, 128><<<dim3(4, 256, 1), 256, S128>>>(
      nullptr, in_proj_w, in_proj_b, nullptr, nullptr, nullptr);
  gemm_k<1, 128, 128><<<dim3(8, 256, 1), 256, S128>>>(
      nullptr, in_proj_w + 512 * 512, in_proj_b + 512, nullptr, nullptr, nullptr);
  gemm_k<2, 64, 64><<<dim3(16, 8, 1), 256, S64>>>(
      pos, in_proj_w, in_proj_b, nullptr, nullptr, nullptr);

  gemm_k<3, 128, 128><<<dim3(2, 2, 1024), 256, S128>>>(
      nullptr, nullptr, nullptr, nullptr, nullptr, nullptr);
  gemm_k<4, 128, 128><<<dim3(2, 1, 2048), 256, S128>>>(
      nullptr, nullptr, nullptr, nullptr, pos_indexes, nullptr);
  gemm_k<5, 128, 128><<<dim3(1, 2, 2048), 256, S128>>>(
      nullptr, nullptr, nullptr, nullptr, pos_indexes, nullptr);

  t3_raw_sm_kernel<<<dim3(256, 16), 256, ST3>>>(out + 16777216);

  gemm_k<6, 128, 64><<<dim3(1, 2, 1024), 256, S6>>>(
      nullptr, nullptr, nullptr, nullptr, nullptr, nullptr);
  gemm_k<7, 128, 128><<<dim3(4, 256, 1), 256, S128>>>(
      nullptr, out_w, out_b, feat_left, nullptr, out);
}

// round 10
// speedup vs baseline: 1.0271x; 1.0271x over previous
#include <cuda_runtime.h>
#include <cuda_fp16.h>

static constexpr long kQSize = 256L * 128 * 512;        // 16,777,216
static constexpr long kAttn  = 8L * 256 * 128 * 256;    // 67,108,864

__device__ float g_lnL[kQSize];
__device__ float g_lnR[kQSize];
__device__ float g_q[kQSize];          // [w][n][c], pre-scaled by 0.125
__device__ float g_kv[2 * kQSize];     // [w][n][k(0:512)|v(512:1024)]
__device__ float g_posp[511 * 1024];   // [p][q_r*0.125 (0:512) | k_r (512:1024)]
__device__ float g_vo[kQSize];         // [w][n][c]
__device__ float g_A12[kAttn];         // [e][w][n][v]  scores (fp32)
__device__ float g_T3[kAttn];          // [e][v][w][n]  (fp32)
__device__ __half g_P[kAttn];          // [e][w][n][v]  probs (fp16)

__device__ __forceinline__ float4 ld4(const float* p) {
  return *reinterpret_cast<const float4*>(p);
}
__device__ __forceinline__ unsigned f2tf(float x) {
  unsigned r;
  asm("cvt.rna.tf32.f32 %0, %1;" : "=r"(r) : "f"(x));
  return r;
}
__device__ __forceinline__ void mma8(float (&d)[4], const unsigned (&a)[4],
                                     const unsigned (&b)[2]) {
  asm("mma.sync.aligned.m16n8k8.row.col.f32.tf32.tf32.f32 "
      "{%0,%1,%2,%3}, {%4,%5,%6,%7}, {%8,%9}, {%0,%1,%2,%3};"
      : "+f"(d[0]), "+f"(d[1]), "+f"(d[2]), "+f"(d[3])
      : "r"(a[0]), "r"(a[1]), "r"(a[2]), "r"(a[3]), "r"(b[0]), "r"(b[1]));
}
__device__ __forceinline__ void cpa16(void* smem_dst, const void* g, bool pred) {
  unsigned d = (unsigned)__cvta_generic_to_shared(smem_dst);
  int sz = pred ? 16 : 0;
  asm volatile("cp.async.cg.shared.global [%0], [%1], 16, %2;"
               :: "r"(d), "l"(g), "r"(sz));
}
__device__ __forceinline__ void cpa_commit() {
  asm volatile("cp.async.commit_group;" ::: "memory");
}
__device__ __forceinline__ void cpa_wait1() {
  asm volatile("cp.async.wait_group 1;" ::: "memory");
}

// ---------------- LayerNorm: one block per 512-float row ----------------
__global__ void __launch_bounds__(128) ln_kernel(const float* __restrict__ fl,
                                                 const float* __restrict__ fr,
                                                 const float* __restrict__ lw,
                                                 const float* __restrict__ lb) {
  long row = blockIdx.x;
  const float* src;
  float* dst;
  if (row < 32768) { src = fl + row * 512;           dst = g_lnL + row * 512; }
  else             { src = fr + (row - 32768) * 512; dst = g_lnR + (row - 32768) * 512; }
  int t = threadIdx.x;
  float4 x = ld4(src + t * 4);
  float s  = x.x + x.y + x.z + x.w;
  float q2 = x.x * x.x + x.y * x.y + x.z * x.z + x.w * x.w;
#pragma unroll
  for (int o = 16; o > 0; o >>= 1) {
    s  += __shfl_xor_sync(0xffffffffu, s, o);
    q2 += __shfl_xor_sync(0xffffffffu, q2, o);
  }
  __shared__ float ss[4], sq[4];
  if ((t & 31) == 0) { ss[t >> 5] = s; sq[t >> 5] = q2; }
  __syncthreads();
  s  = ss[0] + ss[1] + ss[2] + ss[3];
  q2 = sq[0] + sq[1] + sq[2] + sq[3];
  float mean = s * (1.f / 512.f);
  float var  = q2 * (1.f / 512.f) - mean * mean;
  float rstd = rsqrtf(var + 1e-5f);
  float4 wv = ld4(lw + t * 4), bv = ld4(lb + t * 4);
  float4 o;
  o.x = (x.x - mean) * rstd * wv.x + bv.x;
  o.y = (x.y - mean) * rstd * wv.y + bv.y;
  o.z = (x.z - mean) * rstd * wv.z + bv.z;
  o.w = (x.w - mean) * rstd * wv.w + bv.w;
  *reinterpret_cast<float4*>(dst + t * 4) = o;
}

// ------------- Tensor-core tf32 GEMM, 3-stage cp.async pipeline -------------
// 0: q = lnL@Wq^T (+b)*0.125 -> g_q         1: kv = lnR@Wkv^T + b -> g_kv
// 2: posp = pos@W[:1024]^T + b (cols<512 *0.125), M=511 guarded -> g_posp
// 3: T1 per (n,e): q.k^T -> A12             4: T2 per (e,w): q.kr^T += A12 (gather B)
// 5: T3 per (e,v): qr.k^T -> T3 (gather A)  6: AV per (n,e): P(fp16)@V (NN) -> g_vo
// 7: out = vo@Wo^T + b + resid -> d_out
template <int MODE, int BM, int BN>
__global__ void __launch_bounds__(256)
gemm_k(const float* __restrict__ pA, const float* __restrict__ pB,
       const float* __restrict__ pbias, const float* __restrict__ presid,
       const int* __restrict__ pidx, float* __restrict__ pC) {
  constexpr int WGN = BN / 32;       // warps along n
  constexpr int WGM = 8 / WGN;       // warps along m
  constexpr int WM  = BM / WGM;      // rows per warp
  constexpr int MT  = WM / 16;       // 16-row mma tiles per warp
  constexpr int ASZ  = BM * 20;      // float units per A stage (MODE != 6)
  constexpr int ASZH = BM * 24;      // half units per A stage (MODE == 6)
  constexpr int AFLOATS = (MODE == 6) ? (3 * ASZH) / 2 : 3 * ASZ;
  constexpr int BSZ = (MODE == 6) ? 16 * 136 : BN * 20;
  constexpr int NA  = (BM * 16) / 1024;   // cp.async per thread (A, float path)
  constexpr int NB  = (BN * 16) / 1024;   // cp.async per thread (B)
  extern __shared__ float dsm[];
  float*  Asm  = dsm;
  __half* AsmH = reinterpret_cast<__half*>(dsm);
  float*  Bsm  = dsm + AFLOATS;

  const int tid   = threadIdx.x;
  const int warp  = tid >> 5;
  const int lane  = tid & 31;
  const int gid   = lane >> 2;
  const int tg    = lane & 3;
  const int wm0   = (warp / WGN) * WM;
  const int wn0   = (warp % WGN) * 32;
  const int i0 = blockIdx.y * BM;
  const int j0 = blockIdx.x * BN;
  const int z  = blockIdx.z;

  const float*  A  = nullptr;
  const __half* Ah = nullptr;
  const float*  B  = nullptr;
  float* C = nullptr;
  long lda = 0, ldb = 0, ldc = 0;
  int K = 0, e = 0, bb = 0;

  if constexpr (MODE == 0) { A = g_lnL; lda = 512; K = 512; B = pB; ldb = 512; C = g_q; ldc = 512; }
  else if constexpr (MODE == 1) { A = g_lnR; lda = 512; K = 512; B = pB; ldb = 512; C = g_kv; ldc = 1024; }
  else if constexpr (MODE == 2) { A = pA; lda = 512; K = 512; B = pB; ldb = 512; C = g_posp; ldc = 1024; }
  else if constexpr (MODE == 3) { bb = z >> 3; e = z & 7;
    A = g_q + (long)bb * 512 + e * 64; lda = 65536; K = 64;
    B = g_kv + (long)bb * 1024 + e * 64; ldb = 131072;
    C = g_A12 + (long)e * 8388608 + (long)bb * 256; ldc = 32768; }
  else if constexpr (MODE == 4) { e = z >> 8; bb = z & 255;
    A = g_q + (long)bb * 65536 + e * 64; lda = 512; K = 64;
    C = g_A12 + (long)e * 8388608 + (long)bb * 32768; ldc = 256; }
  else if constexpr (MODE == 5) { e = z >> 8; bb = z & 255;
    B = g_kv + (long)bb * 131072 + e * 64; ldb = 1024; K = 64;
    C = g_T3 + ((long)e * 256 + bb) * 32768; ldc = 128; }
  else if constexpr (MODE == 6) { bb = z >> 3; e = z & 7;
    Ah = g_P + (long)e * 8388608 + (long)bb * 256; lda = 32768; K = 256;
    B = g_kv + (long)bb * 1024 + 512 + e * 64; ldb = 131072;
    C = g_vo + (long)bb * 512 + e * 64; ldc = 65536; }
  else { A = g_vo; lda = 512; K = 512; B = pB; ldb = 512; C = pC; ldc = 512; }

  auto issue_tiles = [&](int k0, int stage) {
    if constexpr (MODE == 6) {
      __half* dstA = AsmH + stage * ASZH;
      int t = tid * 8;                 // half index; 256 thr * 8 = 2048 = 128*16
      int i = t >> 4, kk = t & 15;
      cpa16(&dstA[i * 24 + kk], Ah + (long)(i0 + i) * lda + k0 + kk, true);
    } else {
      float* dstA = Asm + stage * ASZ;
#pragma unroll
      for (int it = 0; it < NA; ++it) {
        int t = (tid + it * 256) * 4;
        int i = t >> 4, kk = t & 15;
        float* d = &dstA[i * 20 + kk];
        if constexpr (MODE == 5) {
          int gi = pidx[(i0 + i) * 256 + bb];
          cpa16(d, g_posp + (long)gi * 1024 + e * 64 + k0 + kk, true);
        } else if constexpr (MODE == 2) {
          cpa16(d, A + (long)(i0 + i) * lda + k0 + kk, i0 + i < 511);
        } else {
          cpa16(d, A + (long)(i0 + i) * lda + k0 + kk, true);
        }
      }
    }
    float* dstB = Bsm + stage * BSZ;
#pragma unroll
    for (int it = 0; it < NB; ++it) {
      int t = (tid + it * 256) * 4;
      if constexpr (MODE == 6) {
        int kk = t / BN, j = t % BN;
        cpa16(&dstB[kk * 136 + j], B + (long)(k0 + kk) * ldb + j0 + j, true);
      } else if constexpr (MODE == 4) {
        int j = t >> 4, kk = t & 15;
        int gi = pidx[bb * 256 + j0 + j];
        cpa16(&dstB[j * 20 + kk], g_posp + (long)gi * 1024 + 512 + e * 64 + k0 + kk, true);
      } else {
        int j = t >> 4, kk = t & 15;
        cpa16(&dstB[j * 20 + kk], B + (long)(j0 + j) * ldb + k0 + kk, true);
      }
    }
  };

  float acc[MT][4][4];
#pragma unroll
  for (int m = 0; m < MT; ++m)
#pragma unroll
    for (int n = 0; n < 4; ++n)
#pragma unroll
      for (int r = 0; r < 4; ++r) acc[m][n][r] = 0.f;

  const int NIT = K / 16;
  issue_tiles(0, 0);  cpa_commit();
  issue_tiles(16, 1); cpa_commit();

  for (int itn = 0; itn < NIT; ++itn) {
    cpa_wait1();
    __syncthreads();
    int nxt = itn + 2;
    if (nxt < NIT) issue_tiles(nxt * 16, nxt % 3);
    cpa_commit();

    const int cur = itn % 3;
    const float*  ap  = Asm + cur * ASZ;
    const __half* apH = AsmH + cur * ASZH;
    const float*  bp  = Bsm + cur * BSZ;
#pragma unroll
    for (int ks = 0; ks < 2; ++ks) {
      const int kb = ks * 8;
      unsigned a[MT][4], b[4][2];
#pragma unroll
      for (int mt = 0; mt < MT; ++mt) {
        int r = wm0 + mt * 16 + gid;
        if constexpr (MODE == 6) {
          a[mt][0] = f2tf(__half2float(apH[r * 24 + kb + tg]));
          a[mt][1] = f2tf(__half2float(apH[(r + 8) * 24 + kb + tg]));
          a[mt][2] = f2tf(__half2float(apH[r * 24 + kb + tg + 4]));
          a[mt][3] = f2tf(__half2float(apH[(r + 8) * 24 + kb + tg + 4]));
        } else {
          a[mt][0] = f2tf(ap[r * 20 + kb + tg]);
          a[mt][1] = f2tf(ap[(r + 8) * 20 + kb + tg]);
          a[mt][2] = f2tf(ap[r * 20 + kb + tg + 4]);
          a[mt][3] = f2tf(ap[(r + 8) * 20 + kb + tg + 4]);
        }
      }
#pragma unroll
      for (int nt = 0; nt < 4; ++nt) {
        int cn = wn0 + nt * 8 + gid;
        if constexpr (MODE == 6) {
          b[nt][0] = f2tf(bp[(kb + tg) * 136 + cn]);
          b[nt][1] = f2tf(bp[(kb + tg + 4) * 136 + cn]);
        } else {
          b[nt][0] = f2tf(bp[cn * 20 + kb + tg]);
          b[nt][1] = f2tf(bp[cn * 20 + kb + tg + 4]);
        }
      }
#pragma unroll
      for (int mt = 0; mt < MT; ++mt)
#pragma unroll
        for (int nt = 0; nt < 4; ++nt) mma8(acc[mt][nt], a[mt], b[nt]);
    }
  }

  // ---- epilogue ----
#pragma unroll
  for (int mt = 0; mt < MT; ++mt) {
#pragma unroll
    for (int nt = 0; nt < 4; ++nt) {
      int j = j0 + wn0 + nt * 8 + 2 * tg;
#pragma unroll
      for (int h = 0; h < 2; ++h) {
        int i = i0 + wm0 + mt * 16 + gid + h * 8;
        if constexpr (MODE == 2) { if (i >= 511) continue; }
        float v0 = acc[mt][nt][h * 2 + 0];
        float v1 = acc[mt][nt][h * 2 + 1];
        float* cp = C + (long)i * ldc + j;
        if constexpr (MODE == 0) {
          float2 bv = *reinterpret_cast<const float2*>(pbias + j);
          v0 = (v0 + bv.x) * 0.125f; v1 = (v1 + bv.y) * 0.125f;
        } else if constexpr (MODE == 1) {
          float2 bv = *reinterpret_cast<const float2*>(pbias + j);
          v0 += bv.x; v1 += bv.y;
        } else if constexpr (MODE == 2) {
          float2 bv = *reinterpret_cast<const float2*>(pbias + j);
          float sc = (j < 512) ? 0.125f : 1.0f;
          v0 = (v0 + bv.x) * sc; v1 = (v1 + bv.y) * sc;
        } else if constexpr (MODE == 4) {
          float2 o = *reinterpret_cast<const float2*>(cp);
          v0 += o.x; v1 += o.y;
        } else if constexpr (MODE == 7) {
          float2 bv = *reinterpret_cast<const float2*>(pbias + j);
          float2 rv = *reinterpret_cast<const float2*>(presid + (long)i * 512 + j);
          v0 += bv.x + rv.x; v1 += bv.y + rv.y;
        }
        *reinterpret_cast<float2*>(cp) = make_float2(v0, v1);
      }
    }
  }
}

// ---------------- T3 transpose-add: A12[e][w][n][v] += T3[e][v][w][n] ----------------
__global__ void __launch_bounds__(256) t3_add_kernel() {
  int w = blockIdx.x, e = blockIdx.y;
  __shared__ float ts[32][129];
  long a12base = (long)e * 8388608 + (long)w * 32768;
  long t3base  = (long)e * 256 * 32768 + (long)w * 128;
  for (int v0 = 0; v0 < 256; v0 += 32) {
    for (int t = threadIdx.x; t < 32 * 128; t += 256) {
      int vj = t >> 7, n = t & 127;
      ts[vj][n] = g_T3[t3base + (long)(v0 + vj) * 32768 + n];
    }
    __syncthreads();
    for (int t = threadIdx.x; t < 32 * 128; t += 256) {
      int n = t >> 5, vj = t & 31;
      g_A12[a12base + n * 256 + v0 + vj] += ts[vj][n];
    }
    __syncthreads();
  }
}

// ------- Merged raw_attn + softmax: fp32 scores in, fp16 probs out -------
__global__ void __launch_bounds__(256) raw_sm_kernel(float* __restrict__ out2) {
  const int w    = blockIdx.x;
  const int n    = blockIdx.y * 8 + (threadIdx.x >> 5);
  const int lane = threadIdx.x & 31;

  float raw0 = 0.f, raw1 = 0.f, raw2 = 0.f, raw3 = 0.f;
  float raw4 = 0.f, raw5 = 0.f, raw6 = 0.f, raw7 = 0.f;

#pragma unroll
  for (int e = 0; e < 8; ++e) {
    const float* p = g_A12 + (long)e * 8388608 + (long)w * 32768 + n * 256;
    __half* ph = g_P + (long)e * 8388608 + (long)w * 32768 + n * 256;
    float4 a = ld4(p + lane * 4);
    float4 b = ld4(p + 128 + lane * 4);
    raw0 += a.x; raw1 += a.y; raw2 += a.z; raw3 += a.w;
    raw4 += b.x; raw5 += b.y; raw6 += b.z; raw7 += b.w;
    float mx = fmaxf(fmaxf(fmaxf(a.x, a.y), fmaxf(a.z, a.w)),
                     fmaxf(fmaxf(b.x, b.y), fmaxf(b.z, b.w)));
#pragma unroll
    for (int o = 16; o > 0; o >>= 1) mx = fmaxf(mx, __shfl_xor_sync(0xffffffffu, mx, o));
    a.x = __expf(a.x - mx); a.y = __expf(a.y - mx);
    a.z = __expf(a.z - mx); a.w = __expf(a.w - mx);
    b.x = __expf(b.x - mx); b.y = __expf(b.y - mx);
    b.z = __expf(b.z - mx); b.w = __expf(b.w - mx);
    float s = a.x + a.y + a.z + a.w + b.x + b.y + b.z + b.w;
#pragma unroll
    for (int o = 16; o > 0; o >>= 1) s += __shfl_xor_sync(0xffffffffu, s, o);
    float inv = 1.0f / s;
    __half2 h0 = __floats2half2_rn(a.x * inv, a.y * inv);
    __half2 h1 = __floats2half2_rn(a.z * inv, a.w * inv);
    __half2 h2 = __floats2half2_rn(b.x * inv, b.y * inv);
    __half2 h3 = __floats2half2_rn(b.z * inv, b.w * inv);
    uint2 u0, u1;
    u0.x = *reinterpret_cast<unsigned*>(&h0); u0.y = *reinterpret_cast<unsigned*>(&h1);
    u1.x = *reinterpret_cast<unsigned*>(&h2); u1.y = *reinterpret_cast<unsigned*>(&h3);
    *reinterpret_cast<uint2*>(ph + lane * 4)       = u0;
    *reinterpret_cast<uint2*>(ph + 128 + lane * 4) = u1;
  }

  float* rp = out2 + ((long)n * 256 + w) * 256;
  *reinterpret_cast<float4*>(rp + lane * 4) = make_float4(raw0, raw1, raw2, raw3);
  *reinterpret_cast<float4*>(rp + 128 + lane * 4) = make_float4(raw4, raw5, raw6, raw7);
}

extern "C" void kernel_launch(void* const* d_in, const int* in_sizes, int n_in,
                              void* d_out, int out_size) {
  const float* feat_left   = (const float*)d_in[0];
  const float* feat_right  = (const float*)d_in[1];
  const float* pos         = (const float*)d_in[2];
  const int*   pos_indexes = (const int*)d_in[3];
  const float* ln_w        = (const float*)d_in[4];
  const float* ln_b        = (const float*)d_in[5];
  const float* in_proj_w   = (const float*)d_in[6];
  const float* in_proj_b   = (const float*)d_in[7];
  const float* out_w       = (const float*)d_in[8];
  const float* out_b       = (const float*)d_in[9];
  float* out = (float*)d_out;

  constexpr int S128 = 3 * (128 * 20 + 128 * 20) * 4;    // 61440
  constexpr int S64  = 3 * (64 * 20 + 64 * 20) * 4;      // 30720
  constexpr int S6   = 3 * (128 * 24 * 2 + 16 * 136 * 4);// 44544
  cudaFuncSetAttribute(gemm_k<0, 128, 128>, cudaFuncAttributeMaxDynamicSharedMemorySize, S128);
  cudaFuncSetAttribute(gemm_k<1, 128, 128>, cudaFuncAttributeMaxDynamicSharedMemorySize, S128);
  cudaFuncSetAttribute(gemm_k<3, 128, 128>, cudaFuncAttributeMaxDynamicSharedMemorySize, S128);
  cudaFuncSetAttribute(gemm_k<4, 128, 128>, cudaFuncAttributeMaxDynamicSharedMemorySize, S128);
  cudaFuncSetAttribute(gemm_k<5, 128, 128>, cudaFuncAttributeMaxDynamicSharedMemorySize, S128);
  cudaFuncSetAttribute(gemm_k<7, 128, 128>, cudaFuncAttributeMaxDynamicSharedMemorySize, S128);
  cudaFuncSetAttribute(gemm_k<6, 128, 64>,  cudaFuncAttributeMaxDynamicSharedMemorySize, S6);

  ln_kernel<<<65536, 128>>>(feat_left, feat_right, ln_w, ln_b);

  gemm_k<0, 128, 128><<<dim3(4, 256, 1), 256, S128>>>(
      nullptr, in_proj_w, in_proj_b, nullptr, nullptr, nullptr);
  gemm_k<1, 128, 128><<<dim3(8, 256, 1), 256, S128>>>(
      nullptr, in_proj_w + 512 * 512, in_proj_b + 512, nullptr, nullptr, nullptr);
  gemm_k<2, 64, 64><<<dim3(16, 8, 1), 256, S64>>>(
      pos, in_proj_w, in_proj_b, nullptr, nullptr, nullptr);

  gemm_k<3, 128, 128><<<dim3(2, 2, 1024), 256, S128>>>(
      nullptr, nullptr, nullptr, nullptr, nullptr, nullptr);
  gemm_k<4, 128, 128><<<dim3(2, 1, 2048), 256, S128>>>(
      nullptr, nullptr, nullptr, nullptr, pos_indexes, nullptr);
  gemm_k<5, 128, 128><<<dim3(1, 2, 2048), 256, S128>>>(
      nullptr, nullptr, nullptr, nullptr, pos_indexes, nullptr);

  t3_add_kernel<<<dim3(256, 8), 256>>>();
  raw_sm_kernel<<<dim3(256, 16), 256>>>(out + 16777216);

  gemm_k<6, 128, 64><<<dim3(1, 2, 1024), 256, S6>>>(
      nullptr, nullptr, nullptr, nullptr, nullptr, nullptr);
  gemm_k<7, 128, 128><<<dim3(4, 256, 1), 256, S128>>>(
      nullptr, out_w, out_b, feat_left, nullptr, out);
}

// round 11
// speedup vs baseline: 1.3818x; 1.3453x over previous
#include <cuda_runtime.h>
#include <cuda_fp16.h>

static constexpr long kQSize = 256L * 128 * 512;        // 16,777,216
static constexpr long kAttn  = 8L * 256 * 128 * 256;    // 67,108,864

__device__ __half g_lnL[kQSize];       // LN(left)  fp16
__device__ __half g_lnR[kQSize];       // LN(right) fp16
__device__ __half g_q[kQSize];         // [w][n][c] *0.125, fp16
__device__ __half g_kv[2 * kQSize];    // [w][n][k|v] fp16
__device__ __half g_posp[511 * 1024];  // [p][q_r*0.125 | k_r] fp16
__device__ __half g_vo[kQSize];        // [w][n][c] fp16
__device__ float  g_A12[kAttn];        // logits fp32 (NEVER fp16)
__device__ float  g_T3[kAttn];         // logits fp32
__device__ __half g_P[kAttn];          // probs fp16
__device__ __half g_wih[1536 * 512];   // in_proj_w fp16
__device__ __half g_woh[512 * 512];    // out_w fp16
__device__ __half g_posh[511 * 512];   // pos fp16

__device__ __forceinline__ float4 ld4(const float* p) {
  return *reinterpret_cast<const float4*>(p);
}
__device__ __forceinline__ void mma16(float (&d)[4], const unsigned (&a)[4],
                                      const unsigned (&b)[2]) {
  asm("mma.sync.aligned.m16n8k16.row.col.f32.f16.f16.f32 "
      "{%0,%1,%2,%3}, {%4,%5,%6,%7}, {%8,%9}, {%0,%1,%2,%3};"
      : "+f"(d[0]), "+f"(d[1]), "+f"(d[2]), "+f"(d[3])
      : "r"(a[0]), "r"(a[1]), "r"(a[2]), "r"(a[3]), "r"(b[0]), "r"(b[1]));
}
__device__ __forceinline__ void cpa16(void* smem_dst, const void* g, bool pred) {
  unsigned d = (unsigned)__cvta_generic_to_shared(smem_dst);
  int sz = pred ? 16 : 0;
  asm volatile("cp.async.cg.shared.global [%0], [%1], 16, %2;"
               :: "r"(d), "l"(g), "r"(sz));
}
__device__ __forceinline__ void cpa_commit() {
  asm volatile("cp.async.commit_group;" ::: "memory");
}
__device__ __forceinline__ void cpa_wait1() {
  asm volatile("cp.async.wait_group 1;" ::: "memory");
}
__device__ __forceinline__ void st_h4(__half* p, float4 v) {
  __half2 h01 = __floats2half2_rn(v.x, v.y);
  __half2 h23 = __floats2half2_rn(v.z, v.w);
  uint2 u;
  u.x = *reinterpret_cast<unsigned*>(&h01);
  u.y = *reinterpret_cast<unsigned*>(&h23);
  *reinterpret_cast<uint2*>(p) = u;
}

// ------- Convert weights + pos to fp16 (once per launch, ~1.3M f4) -------
__global__ void __launch_bounds__(256) cvt_kernel(const float* __restrict__ w_in,
                                                  const float* __restrict__ w_out,
                                                  const float* __restrict__ pos) {
  int i = blockIdx.x * 256 + threadIdx.x;  // float4 index
  if (i < 196608) {                        // in_proj_w: 1536*512/4
    st_h4(g_wih + i * 4, ld4(w_in + (long)i * 4));
  } else if (i < 262144) {                 // out_w: 512*512/4
    int j = i - 196608;
    st_h4(g_woh + j * 4, ld4(w_out + (long)j * 4));
  } else if (i < 327552) {                 // pos: 511*512/4
    int k = i - 262144;
    st_h4(g_posh + k * 4, ld4(pos + (long)k * 4));
  }
}

// ---------------- LayerNorm: one block per 512-float row, fp16 out ----------------
__global__ void __launch_bounds__(128) ln_kernel(const float* __restrict__ fl,
                                                 const float* __restrict__ fr,
                                                 const float* __restrict__ lw,
                                                 const float* __restrict__ lb) {
  long row = blockIdx.x;
  const float* src;
  __half* dst;
  if (row < 32768) { src = fl + row * 512;           dst = g_lnL + row * 512; }
  else             { src = fr + (row - 32768) * 512; dst = g_lnR + (row - 32768) * 512; }
  int t = threadIdx.x;
  float4 x = ld4(src + t * 4);
  float s  = x.x + x.y + x.z + x.w;
  float q2 = x.x * x.x + x.y * x.y + x.z * x.z + x.w * x.w;
#pragma unroll
  for (int o = 16; o > 0; o >>= 1) {
    s  += __shfl_xor_sync(0xffffffffu, s, o);
    q2 += __shfl_xor_sync(0xffffffffu, q2, o);
  }
  __shared__ float ss[4], sq[4];
  if ((t & 31) == 0) { ss[t >> 5] = s; sq[t >> 5] = q2; }
  __syncthreads();
  s  = ss[0] + ss[1] + ss[2] + ss[3];
  q2 = sq[0] + sq[1] + sq[2] + sq[3];
  float mean = s * (1.f / 512.f);
  float var  = q2 * (1.f / 512.f) - mean * mean;
  float rstd = rsqrtf(var + 1e-5f);
  float4 wv = ld4(lw + t * 4), bv = ld4(lb + t * 4);
  float4 o;
  o.x = (x.x - mean) * rstd * wv.x + bv.x;
  o.y = (x.y - mean) * rstd * wv.y + bv.y;
  o.z = (x.z - mean) * rstd * wv.z + bv.z;
  o.w = (x.w - mean) * rstd * wv.w + bv.w;
  st_h4(dst + t * 4, o);
}

// ------------- fp16 m16n8k16 GEMM, 3-stage cp.async pipeline -------------
// 0: q = lnL@Wq^T (+b)*0.125 -> g_q(h)      1: kv = lnR@Wkv^T + b -> g_kv(h)
// 2: posp = posh@W[:1024]^T + b (cols<512 *0.125), M=511 -> g_posp(h)
// 3: T1 per (n,e): q.k^T -> A12 f32         4: T2 per (e,w): q.kr^T += A12 f32
// 5: T3 per (e,v): qr.k^T -> T3 f32         6: AV per (n,e): P(h)@V(h) NN -> g_vo(h)
// 7: out = vo@Wo^T + b + resid -> d_out f32
template <int MODE, int BM, int BN>
__global__ void __launch_bounds__(256)
gemm_k(const float* __restrict__ pbias, const float* __restrict__ presid,
       const int* __restrict__ pidx, float* __restrict__ pC) {
  constexpr int WGN = BN / 32;
  constexpr int WGM = 8 / WGN;
  constexpr int WM  = BM / WGM;
  constexpr int MT  = WM / 16;
  constexpr bool NN = (MODE == 6);
  constexpr int ASZ = BM * 24;                 // halves per A stage (16 + 8 pad)
  constexpr int BSZ = NN ? 16 * 72 : BN * 24;  // halves per B stage
  extern __shared__ __half hsm[];
  __half* AsmH = hsm;
  __half* BsmH = hsm + 3 * ASZ;

  const int tid  = threadIdx.x;
  const int warp = tid >> 5;
  const int lane = tid & 31;
  const int gid  = lane >> 2;
  const int tg   = lane & 3;
  const int wm0  = (warp / WGN) * WM;
  const int wn0  = (warp % WGN) * 32;
  const int i0 = blockIdx.y * BM;
  const int j0 = blockIdx.x * BN;
  const int z  = blockIdx.z;

  const __half* A = nullptr;
  const __half* B = nullptr;
  float*  C  = nullptr;
  __half* Ch = nullptr;
  long lda = 0, ldb = 0, ldc = 0;
  int K = 0, e = 0, bb = 0;

  if constexpr (MODE == 0) { A = g_lnL; lda = 512; K = 512; B = g_wih; ldb = 512; Ch = g_q; ldc = 512; }
  else if constexpr (MODE == 1) { A = g_lnR; lda = 512; K = 512; B = g_wih + 512 * 512; ldb = 512; Ch = g_kv; ldc = 1024; }
  else if constexpr (MODE == 2) { A = g_posh; lda = 512; K = 512; B = g_wih; ldb = 512; Ch = g_posp; ldc = 1024; }
  else if constexpr (MODE == 3) { bb = z >> 3; e = z & 7;
    A = g_q + (long)bb * 512 + e * 64; lda = 65536; K = 64;
    B = g_kv + (long)bb * 1024 + e * 64; ldb = 131072;
    C = g_A12 + (long)e * 8388608 + (long)bb * 256; ldc = 32768; }
  else if constexpr (MODE == 4) { e = z >> 8; bb = z & 255;
    A = g_q + (long)bb * 65536 + e * 64; lda = 512; K = 64;
    C = g_A12 + (long)e * 8388608 + (long)bb * 32768; ldc = 256; }
  else if constexpr (MODE == 5) { e = z >> 8; bb = z & 255;
    B = g_kv + (long)bb * 131072 + e * 64; ldb = 1024; K = 64;
    C = g_T3 + ((long)e * 256 + bb) * 32768; ldc = 128; }
  else if constexpr (MODE == 6) { bb = z >> 3; e = z & 7;
    A = g_P + (long)e * 8388608 + (long)bb * 256; lda = 32768; K = 256;
    B = g_kv + (long)bb * 1024 + 512 + e * 64; ldb = 131072;
    Ch = g_vo + (long)bb * 512 + e * 64; ldc = 65536; }
  else { A = g_vo; lda = 512; K = 512; B = g_woh; ldb = 512; C = pC; ldc = 512; }

  auto issue_tiles = [&](int k0, int stage) {
    __half* dstA = AsmH + stage * ASZ;
    constexpr int CA = BM * 2;   // 16B chunks in A tile
#pragma unroll
    for (int it = 0; it < (CA + 255) / 256; ++it) {
      int c = tid + it * 256;
      if (c < CA) {
        int i = c >> 1, kk = (c & 1) * 8;
        __half* d = dstA + i * 24 + kk;
        if constexpr (MODE == 5) {
          int gi = pidx[(i0 + i) * 256 + bb];
          cpa16(d, g_posp + (long)gi * 1024 + e * 64 + k0 + kk, true);
        } else if constexpr (MODE == 2) {
          cpa16(d, A + (long)(i0 + i) * lda + k0 + kk, i0 + i < 511);
        } else {
          cpa16(d, A + (long)(i0 + i) * lda + k0 + kk, true);
        }
      }
    }
    __half* dstB = BsmH + stage * BSZ;
    if constexpr (NN) {
      int c = tid;
      if (c < 2 * BN) {                       // 16 rows x BN halves
        int kk = c >> 3, j = (c & 7) * 8;     // BN=64: 8 chunks/row
        cpa16(dstB + kk * 72 + j, B + (long)(k0 + kk) * ldb + j0 + j, true);
      }
    } else {
      constexpr int CB = BN * 2;
#pragma unroll
      for (int it = 0; it < (CB + 255) / 256; ++it) {
        int c = tid + it * 256;
        if (c < CB) {
          int j = c >> 1, kk = (c & 1) * 8;
          __half* d = dstB + j * 24 + kk;
          if constexpr (MODE == 4) {
            int gi = pidx[bb * 256 + j0 + j];
            cpa16(d, g_posp + (long)gi * 1024 + 512 + e * 64 + k0 + kk, true);
          } else {
            cpa16(d, B + (long)(j0 + j) * ldb + k0 + kk, true);
          }
        }
      }
    }
  };

  float acc[MT][4][4];
#pragma unroll
  for (int m = 0; m < MT; ++m)
#pragma unroll
    for (int n = 0; n < 4; ++n)
#pragma unroll
      for (int r = 0; r < 4; ++r) acc[m][n][r] = 0.f;

  const int NIT = K / 16;
  issue_tiles(0, 0);  cpa_commit();
  issue_tiles(16, 1); cpa_commit();

  for (int itn = 0; itn < NIT; ++itn) {
    cpa_wait1();
    __syncthreads();
    int nxt = itn + 2;
    if (nxt < NIT) issue_tiles(nxt * 16, nxt % 3);
    cpa_commit();

    const __half* ap = AsmH + (itn % 3) * ASZ;
    const __half* bp = BsmH + (itn % 3) * BSZ;
    unsigned a[MT][4], b[4][2];
#pragma unroll
    for (int mt = 0; mt < MT; ++mt) {
      int r = wm0 + mt * 16 + gid;
      a[mt][0] = *reinterpret_cast<const unsigned*>(ap + r * 24 + tg * 2);
      a[mt][1] = *reinterpret_cast<const unsigned*>(ap + (r + 8) * 24 + tg * 2);
      a[mt][2] = *reinterpret_cast<const unsigned*>(ap + r * 24 + 8 + tg * 2);
      a[mt][3] = *reinterpret_cast<const unsigned*>(ap + (r + 8) * 24 + 8 + tg * 2);
    }
#pragma unroll
    for (int nt = 0; nt < 4; ++nt) {
      int cn = wn0 + nt * 8 + gid;
      if constexpr (NN) {
        int kb = tg * 2;
        unsigned short h0 = *reinterpret_cast<const unsigned short*>(bp + kb * 72 + cn);
        unsigned short h1 = *reinterpret_cast<const unsigned short*>(bp + (kb + 1) * 72 + cn);
        unsigned short h2 = *reinterpret_cast<const unsigned short*>(bp + (kb + 8) * 72 + cn);
        unsigned short h3 = *reinterpret_cast<const unsigned short*>(bp + (kb + 9) * 72 + cn);
        b[nt][0] = (unsigned)h0 | ((unsigned)h1 << 16);
        b[nt][1] = (unsigned)h2 | ((unsigned)h3 << 16);
      } else {
        b[nt][0] = *reinterpret_cast<const unsigned*>(bp + cn * 24 + tg * 2);
        b[nt][1] = *reinterpret_cast<const unsigned*>(bp + cn * 24 + 8 + tg * 2);
      }
    }
#pragma unroll
    for (int mt = 0; mt < MT; ++mt)
#pragma unroll
      for (int nt = 0; nt < 4; ++nt) mma16(acc[mt][nt], a[mt], b[nt]);
  }

  // ---- epilogue ----
#pragma unroll
  for (int mt = 0; mt < MT; ++mt) {
#pragma unroll
    for (int nt = 0; nt < 4; ++nt) {
      int j = j0 + wn0 + nt * 8 + 2 * tg;
#pragma unroll
      for (int h = 0; h < 2; ++h) {
        int i = i0 + wm0 + mt * 16 + gid + h * 8;
        if constexpr (MODE == 2) { if (i >= 511) continue; }
        float v0 = acc[mt][nt][h * 2 + 0];
        float v1 = acc[mt][nt][h * 2 + 1];
        if constexpr (MODE == 0) {
          float2 bv = *reinterpret_cast<const float2*>(pbias + j);
          *reinterpret_cast<__half2*>(Ch + (long)i * ldc + j) =
              __floats2half2_rn((v0 + bv.x) * 0.125f, (v1 + bv.y) * 0.125f);
        } else if constexpr (MODE == 1) {
          float2 bv = *reinterpret_cast<const float2*>(pbias + j);
          *reinterpret_cast<__half2*>(Ch + (long)i * ldc + j) =
              __floats2half2_rn(v0 + bv.x, v1 + bv.y);
        } else if constexpr (MODE == 2) {
          float2 bv = *reinterpret_cast<const float2*>(pbias + j);
          float sc = (j < 512) ? 0.125f : 1.0f;
          *reinterpret_cast<__half2*>(Ch + (long)i * ldc + j) =
              __floats2half2_rn((v0 + bv.x) * sc, (v1 + bv.y) * sc);
        } else if constexpr (MODE == 6) {
          *reinterpret_cast<__half2*>(Ch + (long)i * ldc + j) =
              __floats2half2_rn(v0, v1);
        } else if constexpr (MODE == 4) {
          float* cp = C + (long)i * ldc + j;
          float2 o = *reinterpret_cast<const float2*>(cp);
          *reinterpret_cast<float2*>(cp) = make_float2(v0 + o.x, v1 + o.y);
        } else if constexpr (MODE == 7) {
          float2 bv = *reinterpret_cast<const float2*>(pbias + j);
          float2 rv = *reinterpret_cast<const float2*>(presid + (long)i * 512 + j);
          *reinterpret_cast<float2*>(C + (long)i * ldc + j) =
              make_float2(v0 + bv.x + rv.x, v1 + bv.y + rv.y);
        } else {  // modes 3, 5: fp32 logits
          *reinterpret_cast<float2*>(C + (long)i * ldc + j) = make_float2(v0, v1);
        }
      }
    }
  }
}

// ---------------- T3 transpose-add (fp32): A12 += T3^T ----------------
__global__ void __launch_bounds__(256) t3_add_kernel() {
  int w = blockIdx.x, e = blockIdx.y;
  __shared__ float ts[32][129];
  long a12base = (long)e * 8388608 + (long)w * 32768;
  long t3base  = (long)e * 256 * 32768 + (long)w * 128;
  for (int v0 = 0; v0 < 256; v0 += 32) {
    for (int t = threadIdx.x; t < 32 * 128; t += 256) {
      int vj = t >> 7, n = t & 127;
      ts[vj][n] = g_T3[t3base + (long)(v0 + vj) * 32768 + n];
    }
    __syncthreads();
    for (int t = threadIdx.x; t < 32 * 128; t += 256) {
      int n = t >> 5, vj = t & 31;
      g_A12[a12base + n * 256 + v0 + vj] += ts[vj][n];
    }
    __syncthreads();
  }
}

// ------- Merged raw_attn + softmax: fp32 scores in, fp16 probs out -------
__global__ void __launch_bounds__(256) raw_sm_kernel(float* __restrict__ out2) {
  const int w    = blockIdx.x;
  const int n    = blockIdx.y * 8 + (threadIdx.x >> 5);
  const int lane = threadIdx.x & 31;

  float raw0 = 0.f, raw1 = 0.f, raw2 = 0.f, raw3 = 0.f;
  float raw4 = 0.f, raw5 = 0.f, raw6 = 0.f, raw7 = 0.f;

#pragma unroll
  for (int e = 0; e < 8; ++e) {
    const float* p = g_A12 + (long)e * 8388608 + (long)w * 32768 + n * 256;
    __half* ph = g_P + (long)e * 8388608 + (long)w * 32768 + n * 256;
    float4 a = ld4(p + lane * 4);
    float4 b = ld4(p + 128 + lane * 4);
    raw0 += a.x; raw1 += a.y; raw2 += a.z; raw3 += a.w;
    raw4 += b.x; raw5 += b.y; raw6 += b.z; raw7 += b.w;
    float mx = fmaxf(fmaxf(fmaxf(a.x, a.y), fmaxf(a.z, a.w)),
                     fmaxf(fmaxf(b.x, b.y), fmaxf(b.z, b.w)));
#pragma unroll
    for (int o = 16; o > 0; o >>= 1) mx = fmaxf(mx, __shfl_xor_sync(0xffffffffu, mx, o));
    a.x = __expf(a.x - mx); a.y = __expf(a.y - mx);
    a.z = __expf(a.z - mx); a.w = __expf(a.w - mx);
    b.x = __expf(b.x - mx); b.y = __expf(b.y - mx);
    b.z = __expf(b.z - mx); b.w = __expf(b.w - mx);
    float s = a.x + a.y + a.z + a.w + b.x + b.y + b.z + b.w;
#pragma unroll
    for (int o = 16; o > 0; o >>= 1) s += __shfl_xor_sync(0xffffffffu, s, o);
    float inv = 1.0f / s;
    __half2 h0 = __floats2half2_rn(a.x * inv, a.y * inv);
    __half2 h1 = __floats2half2_rn(a.z * inv, a.w * inv);
    __half2 h2 = __floats2half2_rn(b.x * inv, b.y * inv);
    __half2 h3 = __floats2half2_rn(b.z * inv, b.w * inv);
    uint2 u0, u1;
    u0.x = *reinterpret_cast<unsigned*>(&h0); u0.y = *reinterpret_cast<unsigned*>(&h1);
    u1.x = *reinterpret_cast<unsigned*>(&h2); u1.y = *reinterpret_cast<unsigned*>(&h3);
    *reinterpret_cast<uint2*>(ph + lane * 4)       = u0;
    *reinterpret_cast<uint2*>(ph + 128 + lane * 4) = u1;
  }

  float* rp = out2 + ((long)n * 256 + w) * 256;
  *reinterpret_cast<float4*>(rp + lane * 4) = make_float4(raw0, raw1, raw2, raw3);
  *reinterpret_cast<float4*>(rp + 128 + lane * 4) = make_float4(raw4, raw5, raw6, raw7);
}

extern "C" void kernel_launch(void* const* d_in, const int* in_sizes, int n_in,
                              void* d_out, int out_size) {
  const float* feat_left   = (const float*)d_in[0];
  const float* feat_right  = (const float*)d_in[1];
  const float* pos         = (const float*)d_in[2];
  const int*   pos_indexes = (const int*)d_in[3];
  const float* ln_w        = (const float*)d_in[4];
  const float* ln_b        = (const float*)d_in[5];
  const float* in_proj_w   = (const float*)d_in[6];
  const float* in_proj_b   = (const float*)d_in[7];
  const float* out_w       = (const float*)d_in[8];
  const float* out_b       = (const float*)d_in[9];
  float* out = (float*)d_out;

  constexpr int S128 = 3 * (128 * 24 + 128 * 24) * 2;  // 36864
  constexpr int S64  = 3 * (64 * 24 + 64 * 24) * 2;    // 18432
  constexpr int S6   = 3 * (128 * 24 + 16 * 72) * 2;   // 25344

  cvt_kernel<<<1280, 256>>>(in_proj_w, out_w, pos);
  ln_kernel<<<65536, 128>>>(feat_left, feat_right, ln_w, ln_b);

  gemm_k<0, 128, 128><<<dim3(4, 256, 1), 256, S128>>>(
      in_proj_b, nullptr, nullptr, nullptr);
  gemm_k<1, 128, 128><<<dim3(8, 256, 1), 256, S128>>>(
      in_proj_b + 512, nullptr, nullptr, nullptr);
  gemm_k<2, 64, 64><<<dim3(16, 8, 1), 256, S64>>>(
      in_proj_b, nullptr, nullptr, nullptr);

  gemm_k<3, 128, 128><<<dim3(2, 2, 1024), 256, S128>>>(
      nullptr, nullptr, nullptr, nullptr);
  gemm_k<4, 128, 128><<<dim3(2, 1, 2048), 256, S128>>>(
      nullptr, nullptr, pos_indexes, nullptr);
  gemm_k<5, 128, 128><<<dim3(1, 2, 2048), 256, S128>>>(
      nullptr, nullptr, pos_indexes, nullptr);

  t3_add_kernel<<<dim3(256, 8), 256>>>();
  raw_sm_kernel<<<dim3(256, 16), 256>>>(out + 16777216);

  gemm_k<6, 128, 64><<<dim3(1, 2, 1024), 256, S6>>>(
      nullptr, nullptr, nullptr, nullptr);
  gemm_k<7, 128, 128><<<dim3(4, 256, 1), 256, S128>>>(
      out_b, feat_left, nullptr, out);
}

// round 12
// speedup vs baseline: 1.5527x; 1.1237x over previous
#include <cuda_runtime.h>
#include <cuda_fp16.h>

static constexpr long kQSize = 256L * 128 * 512;        // 16,777,216
static constexpr long kAttn  = 8L * 256 * 128 * 256;    // 67,108,864

__device__ __half g_lnL[kQSize];       // LN(left)  fp16
__device__ __half g_lnR[kQSize];       // LN(right) fp16
__device__ __half g_q[kQSize];         // [w][n][c] *0.125, fp16
__device__ __half g_kv[2 * kQSize];    // [w][n][k|v] fp16
__device__ __half g_posp[511 * 1024];  // [p][q_r*0.125 | k_r] fp16
__device__ __half g_vo[kQSize];        // [w][n][c] fp16
__device__ float  g_A12[kAttn];        // logits fp32 (NEVER fp16)
__device__ float  g_T3[kAttn];         // logits fp32
__device__ __half g_P[kAttn];          // probs fp16
__device__ __half g_wih[1536 * 512];   // in_proj_w fp16
__device__ __half g_woh[512 * 512];    // out_w fp16
__device__ __half g_posh[511 * 512];   // pos fp16

__device__ __forceinline__ float4 ld4(const float* p) {
  return *reinterpret_cast<const float4*>(p);
}
__device__ __forceinline__ void mma16(float (&d)[4], const unsigned (&a)[4],
                                      const unsigned (&b)[2]) {
  asm("mma.sync.aligned.m16n8k16.row.col.f32.f16.f16.f32 "
      "{%0,%1,%2,%3}, {%4,%5,%6,%7}, {%8,%9}, {%0,%1,%2,%3};"
      : "+f"(d[0]), "+f"(d[1]), "+f"(d[2]), "+f"(d[3])
      : "r"(a[0]), "r"(a[1]), "r"(a[2]), "r"(a[3]), "r"(b[0]), "r"(b[1]));
}
__device__ __forceinline__ unsigned s2u(const void* p) {
  return (unsigned)__cvta_generic_to_shared(p);
}
__device__ __forceinline__ void ldsm4(unsigned& r0, unsigned& r1, unsigned& r2,
                                      unsigned& r3, unsigned addr) {
  asm volatile("ldmatrix.sync.aligned.m8n8.x4.shared.b16 {%0,%1,%2,%3}, [%4];"
               : "=r"(r0), "=r"(r1), "=r"(r2), "=r"(r3) : "r"(addr));
}
__device__ __forceinline__ void ldsm4t(unsigned& r0, unsigned& r1, unsigned& r2,
                                       unsigned& r3, unsigned addr) {
  asm volatile("ldmatrix.sync.aligned.m8n8.x4.trans.shared.b16 {%0,%1,%2,%3}, [%4];"
               : "=r"(r0), "=r"(r1), "=r"(r2), "=r"(r3) : "r"(addr));
}
__device__ __forceinline__ void cpa16(void* smem_dst, const void* g, bool pred) {
  unsigned d = s2u(smem_dst);
  int sz = pred ? 16 : 0;
  asm volatile("cp.async.cg.shared.global [%0], [%1], 16, %2;"
               :: "r"(d), "l"(g), "r"(sz));
}
__device__ __forceinline__ void cpa_commit() {
  asm volatile("cp.async.commit_group;" ::: "memory");
}
__device__ __forceinline__ void cpa_wait1() {
  asm volatile("cp.async.wait_group 1;" ::: "memory");
}
__device__ __forceinline__ void st_h4(__half* p, float4 v) {
  __half2 h01 = __floats2half2_rn(v.x, v.y);
  __half2 h23 = __floats2half2_rn(v.z, v.w);
  uint2 u;
  u.x = *reinterpret_cast<unsigned*>(&h01);
  u.y = *reinterpret_cast<unsigned*>(&h23);
  *reinterpret_cast<uint2*>(p) = u;
}

// ------- Convert weights + pos to fp16 (once per launch) -------
__global__ void __launch_bounds__(256) cvt_kernel(const float* __restrict__ w_in,
                                                  const float* __restrict__ w_out,
                                                  const float* __restrict__ pos) {
  int i = blockIdx.x * 256 + threadIdx.x;  // float4 index
  if (i < 196608) {
    st_h4(g_wih + i * 4, ld4(w_in + (long)i * 4));
  } else if (i < 262144) {
    int j = i - 196608;
    st_h4(g_woh + j * 4, ld4(w_out + (long)j * 4));
  } else if (i < 327552) {
    int k = i - 262144;
    st_h4(g_posh + k * 4, ld4(pos + (long)k * 4));
  }
}

// ---------------- LayerNorm: one block per 512-float row, fp16 out ----------------
__global__ void __launch_bounds__(128) ln_kernel(const float* __restrict__ fl,
                                                 const float* __restrict__ fr,
                                                 const float* __restrict__ lw,
                                                 const float* __restrict__ lb) {
  long row = blockIdx.x;
  const float* src;
  __half* dst;
  if (row < 32768) { src = fl + row * 512;           dst = g_lnL + row * 512; }
  else             { src = fr + (row - 32768) * 512; dst = g_lnR + (row - 32768) * 512; }
  int t = threadIdx.x;
  float4 x = ld4(src + t * 4);
  float s  = x.x + x.y + x.z + x.w;
  float q2 = x.x * x.x + x.y * x.y + x.z * x.z + x.w * x.w;
#pragma unroll
  for (int o = 16; o > 0; o >>= 1) {
    s  += __shfl_xor_sync(0xffffffffu, s, o);
    q2 += __shfl_xor_sync(0xffffffffu, q2, o);
  }
  __shared__ float ss[4], sq[4];
  if ((t & 31) == 0) { ss[t >> 5] = s; sq[t >> 5] = q2; }
  __syncthreads();
  s  = ss[0] + ss[1] + ss[2] + ss[3];
  q2 = sq[0] + sq[1] + sq[2] + sq[3];
  float mean = s * (1.f / 512.f);
  float var  = q2 * (1.f / 512.f) - mean * mean;
  float rstd = rsqrtf(var + 1e-5f);
  float4 wv = ld4(lw + t * 4), bv = ld4(lb + t * 4);
  float4 o;
  o.x = (x.x - mean) * rstd * wv.x + bv.x;
  o.y = (x.y - mean) * rstd * wv.y + bv.y;
  o.z = (x.z - mean) * rstd * wv.z + bv.z;
  o.w = (x.w - mean) * rstd * wv.w + bv.w;
  st_h4(dst + t * 4, o);
}

// ------- fp16 m16n8k16 GEMM, BK=32, 3-stage cp.async, ldmatrix frags -------
// 0: q = lnL@Wq^T (+b)*0.125 -> g_q(h)      1: kv = lnR@Wkv^T + b -> g_kv(h)
// 2: posp = posh@W[:1024]^T + b (cols<512 *0.125), M=511 -> g_posp(h)
// 3: T1 per (n,e): q.k^T -> A12 f32         4: T2 per (e,w): q.kr^T += A12 f32
// 5: T3 per (e,v): qr.k^T -> T3 f32         6: AV per (n,e): P(h)@V(h) NN -> g_vo(h)
// 7: out = vo@Wo^T + b + resid -> d_out f32
template <int MODE, int BM, int BN>
__global__ void __launch_bounds__(256)
gemm_k(const float* __restrict__ pbias, const float* __restrict__ presid,
       const int* __restrict__ pidx, float* __restrict__ pC) {
  constexpr int WGN = BN / 32;
  constexpr int WGM = 8 / WGN;
  constexpr int WM  = BM / WGM;
  constexpr int MT  = WM / 16;
  constexpr bool NN = (MODE == 6);
  constexpr int AROW = 40;                      // halves per A/B row (32 + 8 pad)
  constexpr int ASZ = BM * AROW;                // halves per A stage
  constexpr int BSZ = NN ? 32 * 72 : BN * AROW; // halves per B stage
  extern __shared__ __half hsm[];
  __half* AsmH = hsm;
  __half* BsmH = hsm + 3 * ASZ;

  const int tid  = threadIdx.x;
  const int warp = tid >> 5;
  const int lane = tid & 31;
  const int gid  = lane >> 2;
  const int tg   = lane & 3;
  const int wm0  = (warp / WGN) * WM;
  const int wn0  = (warp % WGN) * 32;
  const int i0 = blockIdx.y * BM;
  const int j0 = blockIdx.x * BN;
  const int z  = blockIdx.z;

  const __half* A = nullptr;
  const __half* B = nullptr;
  float*  C  = nullptr;
  __half* Ch = nullptr;
  long lda = 0, ldb = 0, ldc = 0;
  int K = 0, e = 0, bb = 0;

  if constexpr (MODE == 0) { A = g_lnL; lda = 512; K = 512; B = g_wih; ldb = 512; Ch = g_q; ldc = 512; }
  else if constexpr (MODE == 1) { A = g_lnR; lda = 512; K = 512; B = g_wih + 512 * 512; ldb = 512; Ch = g_kv; ldc = 1024; }
  else if constexpr (MODE == 2) { A = g_posh; lda = 512; K = 512; B = g_wih; ldb = 512; Ch = g_posp; ldc = 1024; }
  else if constexpr (MODE == 3) { bb = z >> 3; e = z & 7;
    A = g_q + (long)bb * 512 + e * 64; lda = 65536; K = 64;
    B = g_kv + (long)bb * 1024 + e * 64; ldb = 131072;
    C = g_A12 + (long)e * 8388608 + (long)bb * 256; ldc = 32768; }
  else if constexpr (MODE == 4) { e = z >> 8; bb = z & 255;
    A = g_q + (long)bb * 65536 + e * 64; lda = 512; K = 64;
    C = g_A12 + (long)e * 8388608 + (long)bb * 32768; ldc = 256; }
  else if constexpr (MODE == 5) { e = z >> 8; bb = z & 255;
    B = g_kv + (long)bb * 131072 + e * 64; ldb = 1024; K = 64;
    C = g_T3 + ((long)e * 256 + bb) * 32768; ldc = 128; }
  else if constexpr (MODE == 6) { bb = z >> 3; e = z & 7;
    A = g_P + (long)e * 8388608 + (long)bb * 256; lda = 32768; K = 256;
    B = g_kv + (long)bb * 1024 + 512 + e * 64; ldb = 131072;
    Ch = g_vo + (long)bb * 512 + e * 64; ldc = 65536; }
  else { A = g_vo; lda = 512; K = 512; B = g_woh; ldb = 512; C = pC; ldc = 512; }

  auto issue_tiles = [&](int k0, int stage) {
    __half* dstA = AsmH + stage * ASZ;
    constexpr int CA = BM * 4;   // 16B chunks in A tile (BK=32)
#pragma unroll
    for (int it = 0; it < (CA + 255) / 256; ++it) {
      int c = tid + it * 256;
      if (c < CA) {
        int i = c >> 2, kk = (c & 3) * 8;
        __half* d = dstA + i * AROW + kk;
        if constexpr (MODE == 5) {
          int gi = pidx[(i0 + i) * 256 + bb];
          cpa16(d, g_posp + (long)gi * 1024 + e * 64 + k0 + kk, true);
        } else if constexpr (MODE == 2) {
          cpa16(d, A + (long)(i0 + i) * lda + k0 + kk, i0 + i < 511);
        } else {
          cpa16(d, A + (long)(i0 + i) * lda + k0 + kk, true);
        }
      }
    }
    __half* dstB = BsmH + stage * BSZ;
    if constexpr (NN) {
      int c = tid;                            // 32 k-rows x 8 chunks = 256
      int kk = c >> 3, j = (c & 7) * 8;
      cpa16(dstB + kk * 72 + j, B + (long)(k0 + kk) * ldb + j0 + j, true);
    } else {
      constexpr int CB = BN * 4;
#pragma unroll
      for (int it = 0; it < (CB + 255) / 256; ++it) {
        int c = tid + it * 256;
        if (c < CB) {
          int j = c >> 2, kk = (c & 3) * 8;
          __half* d = dstB + j * AROW + kk;
          if constexpr (MODE == 4) {
            int gi = pidx[bb * 256 + j0 + j];
            cpa16(d, g_posp + (long)gi * 1024 + 512 + e * 64 + k0 + kk, true);
          } else {
            cpa16(d, B + (long)(j0 + j) * ldb + k0 + kk, true);
          }
        }
      }
    }
  };

  float acc[MT][4][4];
#pragma unroll
  for (int m = 0; m < MT; ++m)
#pragma unroll
    for (int n = 0; n < 4; ++n)
#pragma unroll
      for (int r = 0; r < 4; ++r) acc[m][n][r] = 0.f;

  const int NIT = K / 32;
  issue_tiles(0, 0);  cpa_commit();
  issue_tiles(32, 1); cpa_commit();

  for (int itn = 0; itn < NIT; ++itn) {
    cpa_wait1();
    __syncthreads();
    int nxt = itn + 2;
    if (nxt < NIT) issue_tiles(nxt * 32, nxt % 3);
    cpa_commit();

    const __half* ap = AsmH + (itn % 3) * ASZ;
    const __half* bp = BsmH + (itn % 3) * BSZ;
#pragma unroll
    for (int ks = 0; ks < 2; ++ks) {
      const int ko = ks * 16;
      unsigned a[MT][4], b[4][2];
      // A fragments: one ldmatrix.x4 per 16x16 tile
      {
        int row_off = lane & 15;
        int kx = ko + ((lane >> 4) << 3);
#pragma unroll
        for (int mt = 0; mt < MT; ++mt) {
          unsigned ad = s2u(ap + (wm0 + mt * 16 + row_off) * AROW + kx);
          ldsm4(a[mt][0], a[mt][1], a[mt][2], a[mt][3], ad);
        }
      }
      // B fragments
      if constexpr (NN) {
        int kr = ko + (lane & 15);
        int cx = (lane >> 4) << 3;
#pragma unroll
        for (int np = 0; np < 2; ++np) {
          unsigned ad = s2u(bp + kr * 72 + wn0 + np * 16 + cx);
          ldsm4t(b[np * 2][0], b[np * 2][1], b[np * 2 + 1][0], b[np * 2 + 1][1], ad);
        }
      } else {
        int row_off = ((lane >> 4) & 1) * 8 + (lane & 7);
        int kx = ko + (((lane >> 3) & 1) << 3);
#pragma unroll
        for (int np = 0; np < 2; ++np) {
          unsigned ad = s2u(bp + (wn0 + np * 16 + row_off) * AROW + kx);
          ldsm4(b[np * 2][0], b[np * 2][1], b[np * 2 + 1][0], b[np * 2 + 1][1], ad);
        }
      }
#pragma unroll
      for (int mt = 0; mt < MT; ++mt)
#pragma unroll
        for (int nt = 0; nt < 4; ++nt) mma16(acc[mt][nt], a[mt], b[nt]);
    }
  }

  // ---- epilogue ----
#pragma unroll
  for (int mt = 0; mt < MT; ++mt) {
#pragma unroll
    for (int nt = 0; nt < 4; ++nt) {
      int j = j0 + wn0 + nt * 8 + 2 * tg;
#pragma unroll
      for (int h = 0; h < 2; ++h) {
        int i = i0 + wm0 + mt * 16 + gid + h * 8;
        if constexpr (MODE == 2) { if (i >= 511) continue; }
        float v0 = acc[mt][nt][h * 2 + 0];
        float v1 = acc[mt][nt][h * 2 + 1];
        if constexpr (MODE == 0) {
          float2 bv = *reinterpret_cast<const float2*>(pbias + j);
          *reinterpret_cast<__half2*>(Ch + (long)i * ldc + j) =
              __floats2half2_rn((v0 + bv.x) * 0.125f, (v1 + bv.y) * 0.125f);
        } else if constexpr (MODE == 1) {
          float2 bv = *reinterpret_cast<const float2*>(pbias + j);
          *reinterpret_cast<__half2*>(Ch + (long)i * ldc + j) =
              __floats2half2_rn(v0 + bv.x, v1 + bv.y);
        } else if constexpr (MODE == 2) {
          float2 bv = *reinterpret_cast<const float2*>(pbias + j);
          float sc = (j < 512) ? 0.125f : 1.0f;
          *reinterpret_cast<__half2*>(Ch + (long)i * ldc + j) =
              __floats2half2_rn((v0 + bv.x) * sc, (v1 + bv.y) * sc);
        } else if constexpr (MODE == 6) {
          *reinterpret_cast<__half2*>(Ch + (long)i * ldc + j) =
              __floats2half2_rn(v0, v1);
        } else if constexpr (MODE == 4) {
          float* cp = C + (long)i * ldc + j;
          float2 o = *reinterpret_cast<const float2*>(cp);
          *reinterpret_cast<float2*>(cp) = make_float2(v0 + o.x, v1 + o.y);
        } else if constexpr (MODE == 7) {
          float2 bv = *reinterpret_cast<const float2*>(pbias + j);
          float2 rv = *reinterpret_cast<const float2*>(presid + (long)i * 512 + j);
          *reinterpret_cast<float2*>(C + (long)i * ldc + j) =
              make_float2(v0 + bv.x + rv.x, v1 + bv.y + rv.y);
        } else {  // modes 3, 5: fp32 logits
          *reinterpret_cast<float2*>(C + (long)i * ldc + j) = make_float2(v0, v1);
        }
      }
    }
  }
}

// ---------------- T3 transpose-add (fp32): A12 += T3^T ----------------
__global__ void __launch_bounds__(256) t3_add_kernel() {
  int w = blockIdx.x, e = blockIdx.y;
  __shared__ float ts[32][129];
  long a12base = (long)e * 8388608 + (long)w * 32768;
  long t3base  = (long)e * 256 * 32768 + (long)w * 128;
  for (int v0 = 0; v0 < 256; v0 += 32) {
    for (int t = threadIdx.x; t < 32 * 128; t += 256) {
      int vj = t >> 7, n = t & 127;
      ts[vj][n] = g_T3[t3base + (long)(v0 + vj) * 32768 + n];
    }
    __syncthreads();
    for (int t = threadIdx.x; t < 32 * 128; t += 256) {
      int n = t >> 5, vj = t & 31;
      g_A12[a12base + n * 256 + v0 + vj] += ts[vj][n];
    }
    __syncthreads();
  }
}

// ------- Merged raw_attn + softmax: fp32 scores in, fp16 probs out -------
__global__ void __launch_bounds__(256) raw_sm_kernel(float* __restrict__ out2) {
  const int w    = blockIdx.x;
  const int n    = blockIdx.y * 8 + (threadIdx.x >> 5);
  const int lane = threadIdx.x & 31;

  float raw0 = 0.f, raw1 = 0.f, raw2 = 0.f, raw3 = 0.f;
  float raw4 = 0.f, raw5 = 0.f, raw6 = 0.f, raw7 = 0.f;

#pragma unroll
  for (int e = 0; e < 8; ++e) {
    const float* p = g_A12 + (long)e * 8388608 + (long)w * 32768 + n * 256;
    __half* ph = g_P + (long)e * 8388608 + (long)w * 32768 + n * 256;
    float4 a = ld4(p + lane * 4);
    float4 b = ld4(p + 128 + lane * 4);
    raw0 += a.x; raw1 += a.y; raw2 += a.z; raw3 += a.w;
    raw4 += b.x; raw5 += b.y; raw6 += b.z; raw7 += b.w;
    float mx = fmaxf(fmaxf(fmaxf(a.x, a.y), fmaxf(a.z, a.w)),
                     fmaxf(fmaxf(b.x, b.y), fmaxf(b.z, b.w)));
#pragma unroll
    for (int o = 16; o > 0; o >>= 1) mx = fmaxf(mx, __shfl_xor_sync(0xffffffffu, mx, o));
    a.x = __expf(a.x - mx); a.y = __expf(a.y - mx);
    a.z = __expf(a.z - mx); a.w = __expf(a.w - mx);
    b.x = __expf(b.x - mx); b.y = __expf(b.y - mx);
    b.z = __expf(b.z - mx); b.w = __expf(b.w - mx);
    float s = a.x + a.y + a.z + a.w + b.x + b.y + b.z + b.w;
#pragma unroll
    for (int o = 16; o > 0; o >>= 1) s += __shfl_xor_sync(0xffffffffu, s, o);
    float inv = 1.0f / s;
    __half2 h0 = __floats2half2_rn(a.x * inv, a.y * inv);
    __half2 h1 = __floats2half2_rn(a.z * inv, a.w * inv);
    __half2 h2 = __floats2half2_rn(b.x * inv, b.y * inv);
    __half2 h3 = __floats2half2_rn(b.z * inv, b.w * inv);
    uint2 u0, u1;
    u0.x = *reinterpret_cast<unsigned*>(&h0); u0.y = *reinterpret_cast<unsigned*>(&h1);
    u1.x = *reinterpret_cast<unsigned*>(&h2); u1.y = *reinterpret_cast<unsigned*>(&h3);
    *reinterpret_cast<uint2*>(ph + lane * 4)       = u0;
    *reinterpret_cast<uint2*>(ph + 128 + lane * 4) = u1;
  }

  float* rp = out2 + ((long)n * 256 + w) * 256;
  *reinterpret_cast<float4*>(rp + lane * 4) = make_float4(raw0, raw1, raw2, raw3);
  *reinterpret_cast<float4*>(rp + 128 + lane * 4) = make_float4(raw4, raw5, raw6, raw7);
}

extern "C" void kernel_launch(void* const* d_in, const int* in_sizes, int n_in,
                              void* d_out, int out_size) {
  const float* feat_left   = (const float*)d_in[0];
  const float* feat_right  = (const float*)d_in[1];
  const float* pos         = (const float*)d_in[2];
  const int*   pos_indexes = (const int*)d_in[3];
  const float* ln_w        = (const float*)d_in[4];
  const float* ln_b        = (const float*)d_in[5];
  const float* in_proj_w   = (const float*)d_in[6];
  const float* in_proj_b   = (const float*)d_in[7];
  const float* out_w       = (const float*)d_in[8];
  const float* out_b       = (const float*)d_in[9];
  float* out = (float*)d_out;

  constexpr int S128 = 3 * (128 * 40 + 128 * 40) * 2;  // 61440
  constexpr int S64  = 3 * (64 * 40 + 64 * 40) * 2;    // 30720
  constexpr int S6   = 3 * (128 * 40 + 32 * 72) * 2;   // 44544
  cudaFuncSetAttribute(gemm_k<0, 128, 128>, cudaFuncAttributeMaxDynamicSharedMemorySize, S128);
  cudaFuncSetAttribute(gemm_k<1, 128, 128>, cudaFuncAttributeMaxDynamicSharedMemorySize, S128);
  cudaFuncSetAttribute(gemm_k<3, 128, 128>, cudaFuncAttributeMaxDynamicSharedMemorySize, S128);
  cudaFuncSetAttribute(gemm_k<4, 128, 128>, cudaFuncAttributeMaxDynamicSharedMemorySize, S128);
  cudaFuncSetAttribute(gemm_k<5, 128, 128>, cudaFuncAttributeMaxDynamicSharedMemorySize, S128);
  cudaFuncSetAttribute(gemm_k<7, 128, 128>, cudaFuncAttributeMaxDynamicSharedMemorySize, S128);
  cudaFuncSetAttribute(gemm_k<6, 128, 64>,  cudaFuncAttributeMaxDynamicSharedMemorySize, S6);

  cvt_kernel<<<1280, 256>>>(in_proj_w, out_w, pos);
  ln_kernel<<<65536, 128>>>(feat_left, feat_right, ln_w, ln_b);

  gemm_k<0, 128, 128><<<dim3(4, 256, 1), 256, S128>>>(
      in_proj_b, nullptr, nullptr, nullptr);
  gemm_k<1, 128, 128><<<dim3(8, 256, 1), 256, S128>>>(
      in_proj_b + 512, nullptr, nullptr, nullptr);
  gemm_k<2, 64, 64><<<dim3(16, 8, 1), 256, S64>>>(
      in_proj_b, nullptr, nullptr, nullptr);

  gemm_k<3, 128, 128><<<dim3(2, 2, 1024), 256, S128>>>(
      nullptr, nullptr, nullptr, nullptr);
  gemm_k<4, 128, 128><<<dim3(2, 1, 2048), 256, S128>>>(
      nullptr, nullptr, pos_indexes, nullptr);
  gemm_k<5, 128, 128><<<dim3(1, 2, 2048), 256, S128>>>(
      nullptr, nullptr, pos_indexes, nullptr);

  t3_add_kernel<<<dim3(256, 8), 256>>>();
  raw_sm_kernel<<<dim3(256, 16), 256>>>(out + 16777216);

  gemm_k<6, 128, 64><<<dim3(1, 2, 1024), 256, S6>>>(
      nullptr, nullptr, nullptr, nullptr);
  gemm_k<7, 128, 128><<<dim3(4, 256, 1), 256, S128>>>(
      out_b, feat_left, nullptr, out);
}

// round 13
// speedup vs baseline: 1.7738x; 1.1424x over previous
#include <cuda_runtime.h>
#include <cuda_fp16.h>

static constexpr long kQSize = 256L * 128 * 512;        // 16,777,216
static constexpr long kAttn  = 8L * 256 * 128 * 256;    // 67,108,864

__device__ __half g_lnL[kQSize];       // LN(left)  fp16
__device__ __half g_lnR[kQSize];       // LN(right) fp16
__device__ __half g_q[kQSize];         // [w][n][c] *0.125, fp16
__device__ __half g_kv[2 * kQSize];    // [w][n][k|v] fp16
__device__ __half g_posp[511 * 1024];  // [p][q_r*0.125 | k_r] fp16
__device__ __half g_vo[kQSize];        // [w][n][c] fp16
__device__ float  g_A12[kAttn];        // logits fp32 (NEVER fp16)
__device__ float  g_T3[kAttn];         // logits fp32, layout [e][w][v][n]
__device__ __half g_P[kAttn];          // probs fp16  [e][w][n][v]
__device__ __half g_wih[1536 * 512];   // in_proj_w fp16
__device__ __half g_woh[512 * 512];    // out_w fp16
__device__ __half g_posh[511 * 512];   // pos fp16

__device__ __forceinline__ float4 ld4(const float* p) {
  return *reinterpret_cast<const float4*>(p);
}
__device__ __forceinline__ void mma16(float (&d)[4], const unsigned (&a)[4],
                                      const unsigned (&b)[2]) {
  asm("mma.sync.aligned.m16n8k16.row.col.f32.f16.f16.f32 "
      "{%0,%1,%2,%3}, {%4,%5,%6,%7}, {%8,%9}, {%0,%1,%2,%3};"
      : "+f"(d[0]), "+f"(d[1]), "+f"(d[2]), "+f"(d[3])
      : "r"(a[0]), "r"(a[1]), "r"(a[2]), "r"(a[3]), "r"(b[0]), "r"(b[1]));
}
__device__ __forceinline__ unsigned s2u(const void* p) {
  return (unsigned)__cvta_generic_to_shared(p);
}
__device__ __forceinline__ void ldsm4(unsigned& r0, unsigned& r1, unsigned& r2,
                                      unsigned& r3, unsigned addr) {
  asm volatile("ldmatrix.sync.aligned.m8n8.x4.shared.b16 {%0,%1,%2,%3}, [%4];"
               : "=r"(r0), "=r"(r1), "=r"(r2), "=r"(r3) : "r"(addr));
}
__device__ __forceinline__ void ldsm4t(unsigned& r0, unsigned& r1, unsigned& r2,
                                       unsigned& r3, unsigned addr) {
  asm volatile("ldmatrix.sync.aligned.m8n8.x4.trans.shared.b16 {%0,%1,%2,%3}, [%4];"
               : "=r"(r0), "=r"(r1), "=r"(r2), "=r"(r3) : "r"(addr));
}
__device__ __forceinline__ void cpa16(void* smem_dst, const void* g, bool pred) {
  unsigned d = s2u(smem_dst);
  int sz = pred ? 16 : 0;
  asm volatile("cp.async.cg.shared.global [%0], [%1], 16, %2;"
               :: "r"(d), "l"(g), "r"(sz));
}
__device__ __forceinline__ void cpa_commit() {
  asm volatile("cp.async.commit_group;" ::: "memory");
}
__device__ __forceinline__ void cpa_wait1() {
  asm volatile("cp.async.wait_group 1;" ::: "memory");
}
__device__ __forceinline__ void st_h4(__half* p, float4 v) {
  __half2 h01 = __floats2half2_rn(v.x, v.y);
  __half2 h23 = __floats2half2_rn(v.z, v.w);
  uint2 u;
  u.x = *reinterpret_cast<unsigned*>(&h01);
  u.y = *reinterpret_cast<unsigned*>(&h23);
  *reinterpret_cast<uint2*>(p) = u;
}

// ------- Convert weights + pos to fp16 (once per launch) -------
__global__ void __launch_bounds__(256) cvt_kernel(const float* __restrict__ w_in,
                                                  const float* __restrict__ w_out,
                                                  const float* __restrict__ pos) {
  int i = blockIdx.x * 256 + threadIdx.x;  // float4 index
  if (i < 196608) {
    st_h4(g_wih + i * 4, ld4(w_in + (long)i * 4));
  } else if (i < 262144) {
    int j = i - 196608;
    st_h4(g_woh + j * 4, ld4(w_out + (long)j * 4));
  } else if (i < 327552) {
    int k = i - 262144;
    st_h4(g_posh + k * 4, ld4(pos + (long)k * 4));
  }
}

// ---------------- LayerNorm: one block per 512-float row, fp16 out ----------------
__global__ void __launch_bounds__(128) ln_kernel(const float* __restrict__ fl,
                                                 const float* __restrict__ fr,
                                                 const float* __restrict__ lw,
                                                 const float* __restrict__ lb) {
  long row = blockIdx.x;
  const float* src;
  __half* dst;
  if (row < 32768) { src = fl + row * 512;           dst = g_lnL + row * 512; }
  else             { src = fr + (row - 32768) * 512; dst = g_lnR + (row - 32768) * 512; }
  int t = threadIdx.x;
  float4 x = ld4(src + t * 4);
  float s  = x.x + x.y + x.z + x.w;
  float q2 = x.x * x.x + x.y * x.y + x.z * x.z + x.w * x.w;
#pragma unroll
  for (int o = 16; o > 0; o >>= 1) {
    s  += __shfl_xor_sync(0xffffffffu, s, o);
    q2 += __shfl_xor_sync(0xffffffffu, q2, o);
  }
  __shared__ float ss[4], sq[4];
  if ((t & 31) == 0) { ss[t >> 5] = s; sq[t >> 5] = q2; }
  __syncthreads();
  s  = ss[0] + ss[1] + ss[2] + ss[3];
  q2 = sq[0] + sq[1] + sq[2] + sq[3];
  float mean = s * (1.f / 512.f);
  float var  = q2 * (1.f / 512.f) - mean * mean;
  float rstd = rsqrtf(var + 1e-5f);
  float4 wv = ld4(lw + t * 4), bv = ld4(lb + t * 4);
  float4 o;
  o.x = (x.x - mean) * rstd * wv.x + bv.x;
  o.y = (x.y - mean) * rstd * wv.y + bv.y;
  o.z = (x.z - mean) * rstd * wv.z + bv.z;
  o.w = (x.w - mean) * rstd * wv.w + bv.w;
  st_h4(dst + t * 4, o);
}

// ------- fp16 m16n8k16 GEMM, BK=32, 3-stage cp.async, ldmatrix frags -------
// 0: q = lnL@Wq^T (+b)*0.125 -> g_q(h)      1: kv = lnR@Wkv^T + b -> g_kv(h)
// 2: posp = posh@W[:1024]^T + b (cols<512 *0.125), M=511 -> g_posp(h)
// 3: T1 per (n,e): q.k^T -> A12 f32         4: T2 per (e,w): q.kr^T += A12 f32
// 5: T3 per (e,v): qr.k^T -> T3[e][w][v][n] f32
// 6: AV per (n,e): P(h)@V(h) NN -> g_vo(h)  7: out = vo@Wo^T + b + resid -> f32
template <int MODE, int BM, int BN>
__global__ void __launch_bounds__(256)
gemm_k(const float* __restrict__ pbias, const float* __restrict__ presid,
       const int* __restrict__ pidx, float* __restrict__ pC) {
  constexpr int WGN = BN / 32;
  constexpr int WGM = 8 / WGN;
  constexpr int WM  = BM / WGM;
  constexpr int MT  = WM / 16;
  constexpr bool NN = (MODE == 6);
  constexpr int AROW = 40;                      // halves per A/B row (32 + 8 pad)
  constexpr int ASZ = BM * AROW;
  constexpr int BSZ = NN ? 32 * 72 : BN * AROW;
  extern __shared__ __half hsm[];
  __half* AsmH = hsm;
  __half* BsmH = hsm + 3 * ASZ;

  const int tid  = threadIdx.x;
  const int warp = tid >> 5;
  const int lane = tid & 31;
  const int gid  = lane >> 2;
  const int tg   = lane & 3;
  const int wm0  = (warp / WGN) * WM;
  const int wn0  = (warp % WGN) * 32;
  const int i0 = blockIdx.y * BM;
  const int j0 = blockIdx.x * BN;
  const int z  = blockIdx.z;

  const __half* A = nullptr;
  const __half* B = nullptr;
  float*  C  = nullptr;
  __half* Ch = nullptr;
  long lda = 0, ldb = 0, ldc = 0;
  int K = 0, e = 0, bb = 0;

  if constexpr (MODE == 0) { A = g_lnL; lda = 512; K = 512; B = g_wih; ldb = 512; Ch = g_q; ldc = 512; }
  else if constexpr (MODE == 1) { A = g_lnR; lda = 512; K = 512; B = g_wih + 512 * 512; ldb = 512; Ch = g_kv; ldc = 1024; }
  else if constexpr (MODE == 2) { A = g_posh; lda = 512; K = 512; B = g_wih; ldb = 512; Ch = g_posp; ldc = 1024; }
  else if constexpr (MODE == 3) { bb = z >> 3; e = z & 7;
    A = g_q + (long)bb * 512 + e * 64; lda = 65536; K = 64;
    B = g_kv + (long)bb * 1024 + e * 64; ldb = 131072;
    C = g_A12 + (long)e * 8388608 + (long)bb * 256; ldc = 32768; }
  else if constexpr (MODE == 4) { e = z >> 8; bb = z & 255;
    A = g_q + (long)bb * 65536 + e * 64; lda = 512; K = 64;
    C = g_A12 + (long)e * 8388608 + (long)bb * 32768; ldc = 256; }
  else if constexpr (MODE == 5) { e = z >> 8; bb = z & 255;
    B = g_kv + (long)bb * 131072 + e * 64; ldb = 1024; K = 64;
    C = g_T3 + (long)e * 8388608 + bb * 128; ldc = 32768; }   // [e][w][v][n]
  else if constexpr (MODE == 6) { bb = z >> 3; e = z & 7;
    A = g_P + (long)e * 8388608 + (long)bb * 256; lda = 32768; K = 256;
    B = g_kv + (long)bb * 1024 + 512 + e * 64; ldb = 131072;
    Ch = g_vo + (long)bb * 512 + e * 64; ldc = 65536; }
  else { A = g_vo; lda = 512; K = 512; B = g_woh; ldb = 512; C = pC; ldc = 512; }

  auto issue_tiles = [&](int k0, int stage) {
    __half* dstA = AsmH + stage * ASZ;
    constexpr int CA = BM * 4;   // 16B chunks in A tile (BK=32)
#pragma unroll
    for (int it = 0; it < (CA + 255) / 256; ++it) {
      int c = tid + it * 256;
      if (c < CA) {
        int i = c >> 2, kk = (c & 3) * 8;
        __half* d = dstA + i * AROW + kk;
        if constexpr (MODE == 5) {
          int gi = pidx[(i0 + i) * 256 + bb];
          cpa16(d, g_posp + (long)gi * 1024 + e * 64 + k0 + kk, true);
        } else if constexpr (MODE == 2) {
          cpa16(d, A + (long)(i0 + i) * lda + k0 + kk, i0 + i < 511);
        } else {
          cpa16(d, A + (long)(i0 + i) * lda + k0 + kk, true);
        }
      }
    }
    __half* dstB = BsmH + stage * BSZ;
    if constexpr (NN) {
      int c = tid;                            // 32 k-rows x 8 chunks = 256
      int kk = c >> 3, j = (c & 7) * 8;
      cpa16(dstB + kk * 72 + j, B + (long)(k0 + kk) * ldb + j0 + j, true);
    } else {
      constexpr int CB = BN * 4;
#pragma unroll
      for (int it = 0; it < (CB + 255) / 256; ++it) {
        int c = tid + it * 256;
        if (c < CB) {
          int j = c >> 2, kk = (c & 3) * 8;
          __half* d = dstB + j * AROW + kk;
          if constexpr (MODE == 4) {
            int gi = pidx[bb * 256 + j0 + j];
            cpa16(d, g_posp + (long)gi * 1024 + 512 + e * 64 + k0 + kk, true);
          } else {
            cpa16(d, B + (long)(j0 + j) * ldb + k0 + kk, true);
          }
        }
      }
    }
  };

  float acc[MT][4][4];
#pragma unroll
  for (int m = 0; m < MT; ++m)
#pragma unroll
    for (int n = 0; n < 4; ++n)
#pragma unroll
      for (int r = 0; r < 4; ++r) acc[m][n][r] = 0.f;

  const int NIT = K / 32;
  issue_tiles(0, 0);  cpa_commit();
  issue_tiles(32, 1); cpa_commit();

  for (int itn = 0; itn < NIT; ++itn) {
    cpa_wait1();
    __syncthreads();
    int nxt = itn + 2;
    if (nxt < NIT) issue_tiles(nxt * 32, nxt % 3);
    cpa_commit();

    const __half* ap = AsmH + (itn % 3) * ASZ;
    const __half* bp = BsmH + (itn % 3) * BSZ;
#pragma unroll
    for (int ks = 0; ks < 2; ++ks) {
      const int ko = ks * 16;
      unsigned a[MT][4], b[4][2];
      {
        int row_off = lane & 15;
        int kx = ko + ((lane >> 4) << 3);
#pragma unroll
        for (int mt = 0; mt < MT; ++mt) {
          unsigned ad = s2u(ap + (wm0 + mt * 16 + row_off) * AROW + kx);
          ldsm4(a[mt][0], a[mt][1], a[mt][2], a[mt][3], ad);
        }
      }
      if constexpr (NN) {
        int kr = ko + (lane & 15);
        int cx = (lane >> 4) << 3;
#pragma unroll
        for (int np = 0; np < 2; ++np) {
          unsigned ad = s2u(bp + kr * 72 + wn0 + np * 16 + cx);
          ldsm4t(b[np * 2][0], b[np * 2][1], b[np * 2 + 1][0], b[np * 2 + 1][1], ad);
        }
      } else {
        int row_off = ((lane >> 4) & 1) * 8 + (lane & 7);
        int kx = ko + (((lane >> 3) & 1) << 3);
#pragma unroll
        for (int np = 0; np < 2; ++np) {
          unsigned ad = s2u(bp + (wn0 + np * 16 + row_off) * AROW + kx);
          ldsm4(b[np * 2][0], b[np * 2][1], b[np * 2 + 1][0], b[np * 2 + 1][1], ad);
        }
      }
#pragma unroll
      for (int mt = 0; mt < MT; ++mt)
#pragma unroll
        for (int nt = 0; nt < 4; ++nt) mma16(acc[mt][nt], a[mt], b[nt]);
    }
  }

  // ---- epilogue ----
#pragma unroll
  for (int mt = 0; mt < MT; ++mt) {
#pragma unroll
    for (int nt = 0; nt < 4; ++nt) {
      int j = j0 + wn0 + nt * 8 + 2 * tg;
#pragma unroll
      for (int h = 0; h < 2; ++h) {
        int i = i0 + wm0 + mt * 16 + gid + h * 8;
        if constexpr (MODE == 2) { if (i >= 511) continue; }
        float v0 = acc[mt][nt][h * 2 + 0];
        float v1 = acc[mt][nt][h * 2 + 1];
        if constexpr (MODE == 0) {
          float2 bv = *reinterpret_cast<const float2*>(pbias + j);
          *reinterpret_cast<__half2*>(Ch + (long)i * ldc + j) =
              __floats2half2_rn((v0 + bv.x) * 0.125f, (v1 + bv.y) * 0.125f);
        } else if constexpr (MODE == 1) {
          float2 bv = *reinterpret_cast<const float2*>(pbias + j);
          *reinterpret_cast<__half2*>(Ch + (long)i * ldc + j) =
              __floats2half2_rn(v0 + bv.x, v1 + bv.y);
        } else if constexpr (MODE == 2) {
          float2 bv = *reinterpret_cast<const float2*>(pbias + j);
          float sc = (j < 512) ? 0.125f : 1.0f;
          *reinterpret_cast<__half2*>(Ch + (long)i * ldc + j) =
              __floats2half2_rn((v0 + bv.x) * sc, (v1 + bv.y) * sc);
        } else if constexpr (MODE == 6) {
          *reinterpret_cast<__half2*>(Ch + (long)i * ldc + j) =
              __floats2half2_rn(v0, v1);
        } else if constexpr (MODE == 4) {
          float* cp = C + (long)i * ldc + j;
          float2 o = *reinterpret_cast<const float2*>(cp);
          *reinterpret_cast<float2*>(cp) = make_float2(v0 + o.x, v1 + o.y);
        } else if constexpr (MODE == 7) {
          float2 bv = *reinterpret_cast<const float2*>(pbias + j);
          float2 rv = *reinterpret_cast<const float2*>(presid + (long)i * 512 + j);
          *reinterpret_cast<float2*>(C + (long)i * ldc + j) =
              make_float2(v0 + bv.x + rv.x, v1 + bv.y + rv.y);
        } else {  // modes 3, 5: fp32 logits
          *reinterpret_cast<float2*>(C + (long)i * ldc + j) = make_float2(v0, v1);
        }
      }
    }
  }
}

// ------- Fused T3-add + raw_attn + softmax -------
// grid (256 w, 4 n-chunks), block 1024 = 32 warps; warp wi handles n = n0+wi.
// Lane register layout: v = lane + j*32, j<8 (all accesses coalesced).
// T3 layout [e][w][v][n]: staged per e as ts[v][n-chunk] — 128B contiguous runs.
__global__ void __launch_bounds__(1024) t3_raw_sm_kernel(float* __restrict__ out2) {
  __shared__ float ts[256][33];
  const int w    = blockIdx.x;
  const int n0   = blockIdx.y * 32;
  const int tid  = threadIdx.x;
  const int wi   = tid >> 5;
  const int lane = tid & 31;
  const int n    = n0 + wi;

  float raw[8] = {0.f, 0.f, 0.f, 0.f, 0.f, 0.f, 0.f, 0.f};
  const long base_wn = (long)w * 32768 + n * 256;

#pragma unroll 1
  for (int e = 0; e < 8; ++e) {
    __syncthreads();
    const float* src = g_T3 + (long)e * 8388608 + (long)w * 32768 + n0;
#pragma unroll
    for (int it = 0; it < 8; ++it) {
      int c = tid + it * 1024;
      int vj = c >> 5, nn = c & 31;
      ts[vj][nn] = src[(long)vj * 128 + nn];
    }
    __syncthreads();

    const float* p = g_A12 + (long)e * 8388608 + base_wn;
    float x[8];
    float mx = -1e30f;
#pragma unroll
    for (int j = 0; j < 8; ++j) {
      int v = lane + j * 32;
      x[j] = p[v] + ts[v][wi];
      raw[j] += x[j];
      mx = fmaxf(mx, x[j]);
    }
#pragma unroll
    for (int o = 16; o > 0; o >>= 1) mx = fmaxf(mx, __shfl_xor_sync(0xffffffffu, mx, o));
    float s = 0.f;
#pragma unroll
    for (int j = 0; j < 8; ++j) { x[j] = __expf(x[j] - mx); s += x[j]; }
#pragma unroll
    for (int o = 16; o > 0; o >>= 1) s += __shfl_xor_sync(0xffffffffu, s, o);
    float inv = 1.0f / s;
    __half* ph = g_P + (long)e * 8388608 + base_wn;
#pragma unroll
    for (int j = 0; j < 8; ++j) ph[lane + j * 32] = __float2half(x[j] * inv);
  }

  float* rp = out2 + ((long)n * 256 + w) * 256;
#pragma unroll
  for (int j = 0; j < 8; ++j) rp[lane + j * 32] = raw[j];
}

extern "C" void kernel_launch(void* const* d_in, const int* in_sizes, int n_in,
                              void* d_out, int out_size) {
  const float* feat_left   = (const float*)d_in[0];
  const float* feat_right  = (const float*)d_in[1];
  const float* pos         = (const float*)d_in[2];
  const int*   pos_indexes = (const int*)d_in[3];
  const float* ln_w        = (const float*)d_in[4];
  const float* ln_b        = (const float*)d_in[5];
  const float* in_proj_w   = (const float*)d_in[6];
  const float* in_proj_b   = (const float*)d_in[7];
  const float* out_w       = (const float*)d_in[8];
  const float* out_b       = (const float*)d_in[9];
  float* out = (float*)d_out;

  constexpr int S128 = 3 * (128 * 40 + 128 * 40) * 2;  // 61440
  constexpr int S64  = 3 * (64 * 40 + 64 * 40) * 2;    // 30720
  constexpr int S6   = 3 * (128 * 40 + 32 * 72) * 2;   // 44544
  cudaFuncSetAttribute(gemm_k<0, 128, 128>, cudaFuncAttributeMaxDynamicSharedMemorySize, S128);
  cudaFuncSetAttribute(gemm_k<1, 128, 128>, cudaFuncAttributeMaxDynamicSharedMemorySize, S128);
  cudaFuncSetAttribute(gemm_k<3, 128, 128>, cudaFuncAttributeMaxDynamicSharedMemorySize, S128);
  cudaFuncSetAttribute(gemm_k<4, 128, 128>, cudaFuncAttributeMaxDynamicSharedMemorySize, S128);
  cudaFuncSetAttribute(gemm_k<5, 128, 128>, cudaFuncAttributeMaxDynamicSharedMemorySize, S128);
  cudaFuncSetAttribute(gemm_k<7, 128, 128>, cudaFuncAttributeMaxDynamicSharedMemorySize, S128);
  cudaFuncSetAttribute(gemm_k<6, 128, 64>,  cudaFuncAttributeMaxDynamicSharedMemorySize, S6);

  cvt_kernel<<<1280, 256>>>(in_proj_w, out_w, pos);
  ln_kernel<<<65536, 128>>>(feat_left, feat_right, ln_w, ln_b);

  gemm_k<0, 128, 128><<<dim3(4, 256, 1), 256, S128>>>(
      in_proj_b, nullptr, nullptr, nullptr);
  gemm_k<1, 128, 128><<<dim3(8, 256, 1), 256, S128>>>(
      in_proj_b + 512, nullptr, nullptr, nullptr);
  gemm_k<2, 64, 64><<<dim3(16, 8, 1), 256, S64>>>(
      in_proj_b, nullptr, nullptr, nullptr);

  gemm_k<3, 128, 128><<<dim3(2, 2, 1024), 256, S128>>>(
      nullptr, nullptr, nullptr, nullptr);
  gemm_k<4, 128, 128><<<dim3(2, 1, 2048), 256, S128>>>(
      nullptr, nullptr, pos_indexes, nullptr);
  gemm_k<5, 128, 128><<<dim3(1, 2, 2048), 256, S128>>>(
      nullptr, nullptr, pos_indexes, nullptr);

  t3_raw_sm_kernel<<<dim3(256, 4), 1024>>>(out + 16777216);

  gemm_k<6, 128, 64><<<dim3(1, 2, 1024), 256, S6>>>(
      nullptr, nullptr, nullptr, nullptr);
  gemm_k<7, 128, 128><<<dim3(4, 256, 1), 256, S128>>>(
      out_b, feat_left, nullptr, out);
}